// round 3
// baseline (speedup 1.0000x reference)
#include <cuda_runtime.h>

#define FEAT 161
#define HID  176
#define SEQB 456
#define GH   704
#define NTHR 352
#define NBLK 128
#define BT   4

// ---- transposed weight offsets (floats) ----
// layouts: WT[k*Rp + r]
#define O1 0        // Wdh^T : Kp=164, Rp=176
#define O2 28864    // Whr^T : Kp=176, Rp=164
#define O3 57728    // WfrM^T: Kp=164, Rp=164
#define O4 84624    // Wwc^T : Kp=328 (gamma_x seg 164 | m seg 164), Rp=164
#define O5 138416   // [Wih|Whh]^T: Kp=504 (cc 164 | m 164 | h0 176), Rp=704
#define O6 493232   // [Wih2|Whh2]^T: Kp=352 (h0 176 | h 176), Rp=704
#define WT_TOTAL 741040

// ---- bias offsets (floats) ----
#define B_bdh 0
#define B_wdx 176
#define B_bdx 337
#define B_bhr 498
#define B_bfr 659
#define B_bwc 820
#define B_b1  981
#define B_b2  1685
#define B_Wo  2389
#define B_bo  2565
#define B_TOTAL 2566

__device__ float g_WT[WT_TOTAL];
__device__ float g_B[B_TOTAL];
__device__ float g_inv_msum[SEQB];
__device__ float g_lossp[NBLK];

// ============================= repack =====================================
__global__ void repack_kernel(
    const float* __restrict__ Wdh, const float* __restrict__ Whr,
    const float* __restrict__ Wfr, const float* __restrict__ Wwc,
    const float* __restrict__ Wih, const float* __restrict__ Whh,
    const float* __restrict__ Wih2, const float* __restrict__ Whh2,
    const float* __restrict__ bdh, const float* __restrict__ Wdx,
    const float* __restrict__ bdx, const float* __restrict__ bhr,
    const float* __restrict__ bfr, const float* __restrict__ bwc,
    const float* __restrict__ bih, const float* __restrict__ bhh,
    const float* __restrict__ bih2, const float* __restrict__ bhh2,
    const float* __restrict__ Wo, const float* __restrict__ bo)
{
    int stride = gridDim.x * blockDim.x;
    for (int idx = blockIdx.x * blockDim.x + threadIdx.x; idx < WT_TOTAL; idx += stride) {
        float v = 0.0f;
        if (idx < O2) {                       // Wdh^T
            int j = idx - O1, k = j / 176, r = j % 176;
            if (k < 161) v = Wdh[r * 161 + k];
        } else if (idx < O3) {                // Whr^T
            int j = idx - O2, k = j / 164, r = j % 164;
            if (r < 161) v = Whr[r * 176 + k];
        } else if (idx < O4) {                // WfrM^T (off-diag)
            int j = idx - O3, k = j / 164, r = j % 164;
            if (r < 161 && k < 161 && k != r) v = Wfr[r * 161 + k];
        } else if (idx < O5) {                // Wwc^T segmented
            int j = idx - O4, k = j / 164, r = j % 164;
            if (r < 161) {
                if (k < 164) { if (k < 161) v = Wwc[r * 322 + k]; }
                else { int c = k - 164; if (c < 161) v = Wwc[r * 322 + 161 + c]; }
            }
        } else if (idx < O6) {                // [Wih|Whh]^T segmented
            int j = idx - O5, k = j / 704, r = j % 704;
            if (k < 164)      { if (k < 161) v = Wih[r * 322 + k]; }
            else if (k < 328) { int c = k - 164; if (c < 161) v = Wih[r * 322 + 161 + c]; }
            else              { v = Whh[r * 176 + (k - 328)]; }
        } else {                              // [Wih2|Whh2]^T
            int j = idx - O6, k = j / 704, r = j % 704;
            v = (k < 176) ? Wih2[r * 176 + k] : Whh2[r * 176 + (k - 176)];
        }
        g_WT[idx] = v;
    }
    for (int idx = blockIdx.x * blockDim.x + threadIdx.x; idx < B_TOTAL; idx += stride) {
        float v;
        if (idx < 176)        v = bdh[idx];
        else if (idx < 337)   { int f = idx - 176; v = Wdx[f * 161 + f]; }
        else if (idx < 498)   v = bdx[idx - 337];
        else if (idx < 659)   v = bhr[idx - 498];
        else if (idx < 820)   v = bfr[idx - 659];
        else if (idx < 981)   v = bwc[idx - 820];
        else if (idx < 1685)  { int j = idx - 981;  v = bih[j] + bhh[j]; }
        else if (idx < 2389)  { int j = idx - 1685; v = bih2[j] + bhh2[j]; }
        else if (idx < 2565)  v = Wo[idx - 2389];
        else                  v = bo[0];
        g_B[idx] = v;
    }
}

// ========================== msum precompute ===============================
__global__ void msum_kernel(const float* __restrict__ masks)
{
    __shared__ float red[256];
    int t = blockIdx.x;
    float s = 0.0f;
    for (int idx = threadIdx.x; idx < 512 * FEAT; idx += 256) {
        int b = idx / FEAT, f = idx - b * FEAT;
        s += masks[(b * SEQB + t) * FEAT + f];
    }
    red[threadIdx.x] = s;
    __syncthreads();
    for (int o = 128; o > 0; o >>= 1) {
        if (threadIdx.x < o) red[threadIdx.x] += red[threadIdx.x + o];
        __syncthreads();
    }
    if (threadIdx.x == 0) g_inv_msum[t] = 1.0f / (red[0] + 1e-5f);
}

// ========================== GEMV helpers ==================================
__device__ __forceinline__ void gemv_small(float acc[4], const float* __restrict__ wt,
                                           int Rp, int r, const float* __restrict__ in,
                                           int stride, int kp)
{
    const float* wp = wt + r;
    const float* i0 = in;
    const float* i1 = in + stride;
    const float* i2 = in + 2 * stride;
    const float* i3 = in + 3 * stride;
#pragma unroll 2
    for (int k = 0; k < kp; k += 4) {
        float4 x0 = *(const float4*)(i0 + k);
        float4 x1 = *(const float4*)(i1 + k);
        float4 x2 = *(const float4*)(i2 + k);
        float4 x3 = *(const float4*)(i3 + k);
        float w;
        w = wp[0];
        acc[0]=fmaf(w,x0.x,acc[0]); acc[1]=fmaf(w,x1.x,acc[1]); acc[2]=fmaf(w,x2.x,acc[2]); acc[3]=fmaf(w,x3.x,acc[3]);
        w = wp[Rp];
        acc[0]=fmaf(w,x0.y,acc[0]); acc[1]=fmaf(w,x1.y,acc[1]); acc[2]=fmaf(w,x2.y,acc[2]); acc[3]=fmaf(w,x3.y,acc[3]);
        w = wp[2*Rp];
        acc[0]=fmaf(w,x0.z,acc[0]); acc[1]=fmaf(w,x1.z,acc[1]); acc[2]=fmaf(w,x2.z,acc[2]); acc[3]=fmaf(w,x3.z,acc[3]);
        w = wp[3*Rp];
        acc[0]=fmaf(w,x0.w,acc[0]); acc[1]=fmaf(w,x1.w,acc[1]); acc[2]=fmaf(w,x2.w,acc[2]); acc[3]=fmaf(w,x3.w,acc[3]);
        wp += 4 * Rp;
    }
}

#define BIGSTEP(OFS, C) do { float2 w = *(const float2*)(wp + (OFS)); \
    acc[0].x=fmaf(w.x,x0.C,acc[0].x); acc[0].y=fmaf(w.y,x0.C,acc[0].y); \
    acc[1].x=fmaf(w.x,x1.C,acc[1].x); acc[1].y=fmaf(w.y,x1.C,acc[1].y); \
    acc[2].x=fmaf(w.x,x2.C,acc[2].x); acc[2].y=fmaf(w.y,x2.C,acc[2].y); \
    acc[3].x=fmaf(w.x,x3.C,acc[3].x); acc[3].y=fmaf(w.y,x3.C,acc[3].y); } while (0)

__device__ __forceinline__ void gemv_big(float2 acc[4], const float* __restrict__ wt,
                                         int r2, const float* __restrict__ in,
                                         int stride, int kp)
{
    const float* wp = wt + r2;
    const float* i0 = in;
    const float* i1 = in + stride;
    const float* i2 = in + 2 * stride;
    const float* i3 = in + 3 * stride;
#pragma unroll 2
    for (int k = 0; k < kp; k += 4) {
        float4 x0 = *(const float4*)(i0 + k);
        float4 x1 = *(const float4*)(i1 + k);
        float4 x2 = *(const float4*)(i2 + k);
        float4 x3 = *(const float4*)(i3 + k);
        BIGSTEP(0, x);
        BIGSTEP(704, y);
        BIGSTEP(1408, z);
        BIGSTEP(2112, w);
        wp += 4 * 704;
    }
}

// ========================== main persistent kernel ========================
struct __align__(16) SMem {
    float sX[4][164];     // x
    float sM[4][164];     // m
    float sD[4][164];     // deltas, reused as x_c
    float sXh[4][164];    // x_h, reused as c_c
    float sZh[4][164];    // z_h
    float sGamX[4][164];  // gamma_x
    float sH0H[4][352];   // [h0 | h]
    float sC0[4][176];    // LSTM1 cell
    float sC[4][176];     // LSTM2 cell
    float sGate[4][704];  // gate staging / reductions
};

__device__ __forceinline__ float sigf(float x) { return 1.0f / (1.0f + expf(-x)); }

__global__ void __launch_bounds__(NTHR, 1)
brits_kernel(const float* __restrict__ values, const float* __restrict__ masks,
             const float* __restrict__ deltas, float* __restrict__ out)
{
    __shared__ SMem sm;
    const int tid = threadIdx.x;
    const int b0 = blockIdx.x * BT;

    // zero all shared state (h, c, h0, c0 start at 0; pads stay 0 forever)
    {
        float* sp = (float*)&sm;
        for (int i = tid; i < (int)(sizeof(SMem) / 4); i += NTHR) sp[i] = 0.0f;
    }

    // cache per-thread biases
    float r_bdh = 0.f, r_bhr = 0.f, r_bfr = 0.f, r_bwc = 0.f, r_wdx = 0.f, r_bdx = 0.f;
    if (tid < 176) r_bdh = g_B[B_bdh + tid];
    if (tid < 161) { r_bhr = g_B[B_bhr + tid]; r_bfr = g_B[B_bfr + tid]; r_bwc = g_B[B_bwc + tid]; }
    if (tid >= 176 && tid < 337) { r_wdx = g_B[B_wdx + tid - 176]; r_bdx = g_B[B_bdx + tid - 176]; }
    const int r2 = 2 * tid;
    const float r_b1a = g_B[B_b1 + r2], r_b1b = g_B[B_b1 + r2 + 1];
    const float r_b2a = g_B[B_b2 + r2], r_b2b = g_B[B_b2 + r2 + 1];

    float lossAcc = 0.0f;
    __syncthreads();

    for (int t = 0; t < SEQB; t++) {
        const float invms = g_inv_msum[t];

        // P0: load x, m, d
        for (int idx = tid; idx < 4 * 164; idx += NTHR) {
            int b = idx / 164, f = idx - b * 164;
            float xv = 0.f, mv = 0.f, dv = 0.f;
            if (f < 161) {
                int off = ((b0 + b) * SEQB + t) * FEAT + f;
                xv = values[off]; mv = masks[off]; dv = deltas[off];
            }
            sm.sX[b][f] = xv; sm.sM[b][f] = mv; sm.sD[b][f] = dv;
        }
        __syncthreads();

        // P1: gamma_h (decay h) + gamma_x
        if (tid < 176) {
            float acc[4] = {0.f, 0.f, 0.f, 0.f};
            gemv_small(acc, g_WT + O1, 176, tid, &sm.sD[0][0], 164, 164);
#pragma unroll
            for (int b = 0; b < 4; b++) {
                float gh = expf(-fmaxf(acc[b] + r_bdh, 0.0f));
                sm.sH0H[b][176 + tid] *= gh;
            }
        } else if (tid < 337) {
            int f = tid - 176;
#pragma unroll
            for (int b = 0; b < 4; b++)
                sm.sGamX[b][f] = expf(-fmaxf(sm.sD[b][f] * r_wdx + r_bdx, 0.0f));
        }
        __syncthreads();

        // P2: x_h = h @ Whr^T + bhr ; x_c
        if (tid < 161) {
            float acc[4] = {0.f, 0.f, 0.f, 0.f};
            gemv_small(acc, g_WT + O2, 164, tid, &sm.sH0H[0][176], 352, 176);
#pragma unroll
            for (int b = 0; b < 4; b++) {
                float xh = acc[b] + r_bhr;
                sm.sXh[b][tid] = xh;
                float x = sm.sX[b][tid], m = sm.sM[b][tid];
                lossAcc += fabsf(x - xh) * m * invms;
                sm.sD[b][tid] = m * x + (1.0f - m) * xh;   // x_c
            }
        }
        __syncthreads();

        // P3: z_h = x_c @ WfrM^T + bfr
        if (tid < 161) {
            float acc[4] = {0.f, 0.f, 0.f, 0.f};
            gemv_small(acc, g_WT + O3, 164, tid, &sm.sD[0][0], 164, 164);
#pragma unroll
            for (int b = 0; b < 4; b++) {
                float zh = acc[b] + r_bfr;
                sm.sZh[b][tid] = zh;
                lossAcc += fabsf(sm.sX[b][tid] - zh) * sm.sM[b][tid] * invms;
            }
        }
        __syncthreads();

        // P4: alpha, c_h, c_c(+imputation out)
        if (tid < 161) {
            float acc[4] = {0.f, 0.f, 0.f, 0.f};
            gemv_small(acc, g_WT + O4,             164, tid, &sm.sGamX[0][0], 164, 164);
            gemv_small(acc, g_WT + O4 + 164 * 164, 164, tid, &sm.sM[0][0],    164, 164);
#pragma unroll
            for (int b = 0; b < 4; b++) {
                float alpha = acc[b] + r_bwc;
                float ch = alpha * sm.sZh[b][tid] + (1.0f - alpha) * sm.sXh[b][tid];
                float x = sm.sX[b][tid], m = sm.sM[b][tid];
                lossAcc += fabsf(x - ch) * m * invms;
                float cc = m * x + (1.0f - m) * ch;
                sm.sXh[b][tid] = cc;  // reuse as c_c
                out[513 + ((b0 + b) * SEQB + t) * FEAT + tid] = cc;
            }
        }
        __syncthreads();

        // P5: LSTM1 gates
        {
            float2 acc[4] = {{0.f,0.f},{0.f,0.f},{0.f,0.f},{0.f,0.f}};
            gemv_big(acc, g_WT + O5,             r2, &sm.sXh[0][0],  164, 164);
            gemv_big(acc, g_WT + O5 + 164 * 704, r2, &sm.sM[0][0],   164, 164);
            gemv_big(acc, g_WT + O5 + 328 * 704, r2, &sm.sH0H[0][0], 352, 176);
#pragma unroll
            for (int b = 0; b < 4; b++) {
                sm.sGate[b][r2]     = acc[b].x + r_b1a;
                sm.sGate[b][r2 + 1] = acc[b].y + r_b1b;
            }
        }
        __syncthreads();

        // P6: LSTM1 elementwise -> h0, c0
#pragma unroll
        for (int s = 0; s < 2; s++) {
            int item = tid + s * NTHR;
            int b = item / 176, j = item - b * 176;
            float i_ = sigf(sm.sGate[b][j]);
            float f_ = sigf(sm.sGate[b][j + 176]);
            float g_ = tanhf(sm.sGate[b][j + 352]);
            float o_ = sigf(sm.sGate[b][j + 528]);
            float c = f_ * sm.sC0[b][j] + i_ * g_;
            sm.sC0[b][j] = c;
            sm.sH0H[b][j] = o_ * tanhf(c);
        }
        __syncthreads();

        // P7: LSTM2 gates
        {
            float2 acc[4] = {{0.f,0.f},{0.f,0.f},{0.f,0.f},{0.f,0.f}};
            gemv_big(acc, g_WT + O6, r2, &sm.sH0H[0][0], 352, 352);
#pragma unroll
            for (int b = 0; b < 4; b++) {
                sm.sGate[b][r2]     = acc[b].x + r_b2a;
                sm.sGate[b][r2 + 1] = acc[b].y + r_b2b;
            }
        }
        __syncthreads();

        // P8: LSTM2 elementwise -> h, c
#pragma unroll
        for (int s = 0; s < 2; s++) {
            int item = tid + s * NTHR;
            int b = item / 176, j = item - b * 176;
            float i_ = sigf(sm.sGate[b][j]);
            float f_ = sigf(sm.sGate[b][j + 176]);
            float g_ = tanhf(sm.sGate[b][j + 352]);
            float o_ = sigf(sm.sGate[b][j + 528]);
            float c = f_ * sm.sC[b][j] + i_ * g_;
            sm.sC[b][j] = c;
            sm.sH0H[b][176 + j] = o_ * tanhf(c);
        }
        __syncthreads();
    }

    // predictions: sigmoid(h @ Wo^T + bo)
    if (tid < 128) {
        int b = tid >> 5, lane = tid & 31;
        float s = 0.0f;
        for (int j = lane; j < 176; j += 32) s += sm.sH0H[b][176 + j] * g_B[B_Wo + j];
        for (int o = 16; o; o >>= 1) s += __shfl_down_sync(0xffffffffu, s, o);
        if (lane == 0) out[1 + b0 + b] = sigf(s + g_B[B_bo]);
    }

    // loss partial
    {
        float* lr = &sm.sGate[0][0];
        lr[tid] = lossAcc;
        __syncthreads();
        if (tid == 0) {
            float s = 0.0f;
            for (int i = 0; i < NTHR; i++) s += lr[i];
            g_lossp[blockIdx.x] = s;
        }
    }
}

__global__ void finalize_kernel(float* __restrict__ out)
{
    if (threadIdx.x == 0 && blockIdx.x == 0) {
        float s = 0.0f;
        for (int i = 0; i < NBLK; i++) s += g_lossp[i];
        out[0] = s / (float)SEQB;
    }
}

extern "C" void kernel_launch(void* const* d_in, const int* in_sizes, int n_in,
                              void* d_out, int out_size)
{
    const float* values = (const float*)d_in[0];
    const float* masks  = (const float*)d_in[1];
    const float* deltas = (const float*)d_in[2];
    // d_in[3] labels, d_in[4] is_train: unused
    const float* Wdh  = (const float*)d_in[5];
    const float* bdh  = (const float*)d_in[6];
    const float* Wdx  = (const float*)d_in[7];
    const float* bdx  = (const float*)d_in[8];
    const float* Whr  = (const float*)d_in[9];
    const float* bhr  = (const float*)d_in[10];
    const float* Wfr  = (const float*)d_in[11];
    const float* bfr  = (const float*)d_in[12];
    const float* Wwc  = (const float*)d_in[13];
    const float* bwc  = (const float*)d_in[14];
    const float* Wih  = (const float*)d_in[15];
    const float* Whh  = (const float*)d_in[16];
    const float* bih  = (const float*)d_in[17];
    const float* bhh  = (const float*)d_in[18];
    const float* Wih2 = (const float*)d_in[19];
    const float* Whh2 = (const float*)d_in[20];
    const float* bih2 = (const float*)d_in[21];
    const float* bhh2 = (const float*)d_in[22];
    const float* Wo   = (const float*)d_in[23];
    const float* bo   = (const float*)d_in[24];
    float* out = (float*)d_out;

    repack_kernel<<<960, 256>>>(Wdh, Whr, Wfr, Wwc, Wih, Whh, Wih2, Whh2,
                                bdh, Wdx, bdx, bhr, bfr, bwc,
                                bih, bhh, bih2, bhh2, Wo, bo);
    msum_kernel<<<SEQB, 256>>>(masks);
    brits_kernel<<<NBLK, NTHR>>>(values, masks, deltas, out);
    finalize_kernel<<<1, 32>>>(out);
}

// round 4
// speedup vs baseline: 1.0447x; 1.0447x over previous
#include <cuda_runtime.h>

#define FEAT 161
#define HID  176
#define SEQB 456
#define NTHR 352
#define NCTA 128
#define NCLUS 64

// ---- transposed weight offsets (floats) ----
#define O1 0        // Wdh^T : k*176 + r            (K=164, R=176)
#define O2 28864    // Whr^T : k*164 + r            (K=176, R=161)
#define O3 57728    // WfrM^T: k*164 + r            (K=164, R=161)
#define O4 84624    // Wwc^T : k*164 + r, K=328 segmented [gamma_x 164 | m 164]
#define O5 138416   // [Wih|Whh]^T permuted: k*704 + row', K=504 [cc 164|m 164|h0 176]
#define O6 493232   // [Wih2|Whh2]^T permuted: k*704 + row', K=352 [h0 176|h 176]
#define WT_TOTAL 741040

// ---- bias offsets ----
#define B_bdh 0
#define B_wdx 176
#define B_bdx 337
#define B_bhr 498
#define B_bfr 659
#define B_bwc 820
#define B_b1  981
#define B_b2  1685
#define B_Wo  2389
#define B_bo  2565
#define B_TOTAL 2566

#define SMEM_BYTES 75776

__device__ float g_WT[WT_TOTAL];
__device__ float g_B[B_TOTAL];
__device__ float g_inv_msum[SEQB];
__device__ float g_lossp[NCLUS];

// ============================= repack =====================================
__global__ void repack_kernel(
    const float* __restrict__ Wdh, const float* __restrict__ Whr,
    const float* __restrict__ Wfr, const float* __restrict__ Wwc,
    const float* __restrict__ Wih, const float* __restrict__ Whh,
    const float* __restrict__ Wih2, const float* __restrict__ Whh2,
    const float* __restrict__ bdh, const float* __restrict__ Wdx,
    const float* __restrict__ bdx, const float* __restrict__ bhr,
    const float* __restrict__ bfr, const float* __restrict__ bwc,
    const float* __restrict__ bih, const float* __restrict__ bhh,
    const float* __restrict__ bih2, const float* __restrict__ bhh2,
    const float* __restrict__ Wo, const float* __restrict__ bo)
{
    int stride = gridDim.x * blockDim.x;
    for (int idx = blockIdx.x * blockDim.x + threadIdx.x; idx < WT_TOTAL; idx += stride) {
        float v = 0.0f;
        if (idx < O2) {                       // Wdh^T
            int j = idx - O1, k = j / 176, r = j % 176;
            if (k < 161) v = Wdh[r * 161 + k];
        } else if (idx < O3) {                // Whr^T
            int j = idx - O2, k = j / 164, r = j % 164;
            if (r < 161) v = Whr[r * 176 + k];
        } else if (idx < O4) {                // WfrM^T (off-diag)
            int j = idx - O3, k = j / 164, r = j % 164;
            if (r < 161 && k < 161 && k != r) v = Wfr[r * 161 + k];
        } else if (idx < O5) {                // Wwc^T segmented
            int j = idx - O4, k = j / 164, r = j % 164;
            if (r < 161) {
                if (k < 164) { if (k < 161) v = Wwc[r * 322 + k]; }
                else { int c = k - 164; if (c < 161) v = Wwc[r * 322 + 161 + c]; }
            }
        } else if (idx < O6) {                // LSTM1, rows permuted for cluster split
            int j = idx - O5, k = j / 704, rp = j % 704;
            int rk = rp / 352, rem = rp % 352, q = rem / 88, jl = rem % 88;
            int r = q * 176 + rk * 88 + jl;   // original gate row
            if (k < 164)      { if (k < 161) v = Wih[r * 322 + k]; }
            else if (k < 328) { int c = k - 164; if (c < 161) v = Wih[r * 322 + 161 + c]; }
            else              { v = Whh[r * 176 + (k - 328)]; }
        } else {                              // LSTM2 permuted
            int j = idx - O6, k = j / 704, rp = j % 704;
            int rk = rp / 352, rem = rp % 352, q = rem / 88, jl = rem % 88;
            int r = q * 176 + rk * 88 + jl;
            v = (k < 176) ? Wih2[r * 176 + k] : Whh2[r * 176 + (k - 176)];
        }
        g_WT[idx] = v;
    }
    for (int idx = blockIdx.x * blockDim.x + threadIdx.x; idx < B_TOTAL; idx += stride) {
        float v;
        if (idx < 176)        v = bdh[idx];
        else if (idx < 337)   { int f = idx - 176; v = Wdx[f * 161 + f]; }
        else if (idx < 498)   v = bdx[idx - 337];
        else if (idx < 659)   v = bhr[idx - 498];
        else if (idx < 820)   v = bfr[idx - 659];
        else if (idx < 981)   v = bwc[idx - 820];
        else if (idx < 1685)  {
            int j = idx - 981;
            int rk = j / 352, rem = j % 352, q = rem / 88, jl = rem % 88;
            int r = q * 176 + rk * 88 + jl;
            v = bih[r] + bhh[r];
        } else if (idx < 2389) {
            int j = idx - 1685;
            int rk = j / 352, rem = j % 352, q = rem / 88, jl = rem % 88;
            int r = q * 176 + rk * 88 + jl;
            v = bih2[r] + bhh2[r];
        }
        else if (idx < 2565)  v = Wo[idx - 2389];
        else                  v = bo[0];
        g_B[idx] = v;
    }
}

// ========================== msum precompute ===============================
__global__ void msum_kernel(const float* __restrict__ masks)
{
    __shared__ float red[256];
    int t = blockIdx.x;
    float s = 0.0f;
    for (int idx = threadIdx.x; idx < 512 * FEAT; idx += 256) {
        int b = idx / FEAT, f = idx - b * FEAT;
        s += masks[(b * SEQB + t) * FEAT + f];
    }
    red[threadIdx.x] = s;
    __syncthreads();
    for (int o = 128; o > 0; o >>= 1) {
        if (threadIdx.x < o) red[threadIdx.x] += red[threadIdx.x + o];
        __syncthreads();
    }
    if (threadIdx.x == 0) g_inv_msum[t] = 1.0f / (red[0] + 1e-5f);
}

// ========================== helpers =======================================
__device__ __forceinline__ float sigf(float x) { return 1.0f / (1.0f + expf(-x)); }

__device__ __forceinline__ void st_peer(float* p, float v, int peer)
{
    unsigned int a = (unsigned int)__cvta_generic_to_shared(p);
    unsigned int ra;
    asm("mapa.shared::cluster.u32 %0, %1, %2;" : "=r"(ra) : "r"(a), "r"(peer));
    asm volatile("st.shared::cluster.f32 [%0], %1;" :: "r"(ra), "f"(v));
}

#define CSYNC() do { \
    asm volatile("barrier.cluster.arrive.aligned;" ::: "memory"); \
    asm volatile("barrier.cluster.wait.aligned;" ::: "memory"); } while (0)

// scalar K-split partial GEMV, 8 batch, [b][stride] input layout
__device__ __forceinline__ void gemv_part8(float acc[8], const float* __restrict__ wt,
                                           int Rp, int row,
                                           const float* __restrict__ in, int stride,
                                           int k0, int k1)
{
    const float* wp = wt + k0 * Rp + row;
#pragma unroll 2
    for (int k = k0; k < k1; k += 4) {
        float4 x[8];
#pragma unroll
        for (int b = 0; b < 8; b++) x[b] = *(const float4*)(in + b * stride + k);
        float w0 = wp[0], w1 = wp[Rp], w2 = wp[2 * Rp], w3 = wp[3 * Rp];
#pragma unroll
        for (int b = 0; b < 8; b++) {
            acc[b] = fmaf(w0, x[b].x, acc[b]);
            acc[b] = fmaf(w1, x[b].y, acc[b]);
            acc[b] = fmaf(w2, x[b].z, acc[b]);
            acc[b] = fmaf(w3, x[b].w, acc[b]);
        }
        wp += 4 * Rp;
    }
}

// packed f32x2 GEMV: weights stride 704 per k, input pk[K][8] floats
__device__ __forceinline__ void gemv_big_f2(unsigned long long acc[4],
                                            const float* __restrict__ wt, int col,
                                            const float* __restrict__ pk, int kp)
{
    const float* wp = wt + col;
    const unsigned long long* p = (const unsigned long long*)pk;
#pragma unroll 4
    for (int k = 0; k < kp; k += 2) {
        float w0 = wp[0];
        float w1 = wp[704];
        unsigned long long w0p, w1p;
        asm("mov.b64 %0, {%1, %1};" : "=l"(w0p) : "r"(__float_as_uint(w0)));
        asm("mov.b64 %0, {%1, %1};" : "=l"(w1p) : "r"(__float_as_uint(w1)));
#pragma unroll
        for (int bp = 0; bp < 4; bp++)
            asm("fma.rn.f32x2 %0, %1, %2, %0;" : "+l"(acc[bp]) : "l"(w0p), "l"(p[k * 4 + bp]));
#pragma unroll
        for (int bp = 0; bp < 4; bp++)
            asm("fma.rn.f32x2 %0, %1, %2, %0;" : "+l"(acc[bp]) : "l"(w1p), "l"(p[(k + 1) * 4 + bp]));
        wp += 2 * 704;
    }
}

// ========================== main persistent kernel ========================
struct __align__(16) SM8 {
    float sX[8][164], sM[8][164], sD[8][164], sGamX[8][164], sXh[8][164], sZh[8][164];
    float sH[8][176], sH0[8][176];
    float sC0[8][88], sC[8][88];
    float sGate[8][352];
    float pk[504][8];
};

__global__ void __launch_bounds__(NTHR, 1) __cluster_dims__(2, 1, 1)
brits_kernel(const float* __restrict__ values, const float* __restrict__ masks,
             const float* __restrict__ deltas, float* __restrict__ out)
{
    extern __shared__ char dynbuf[];
    SM8* sm = (SM8*)dynbuf;
    const int tid = threadIdx.x;
    unsigned int rank;
    asm("mov.u32 %0, %%cluster_ctarank;" : "=r"(rank));
    const int peer = (int)(rank ^ 1u);
    const int cid = blockIdx.x >> 1;
    const int b0 = cid * 8;

    // zero all shared state
    {
        float* sp = (float*)sm;
        for (int i = tid; i < SMEM_BYTES / 4; i += NTHR) sp[i] = 0.0f;
    }

    float r_bdh = 0.f, r_bhr = 0.f, r_bfr = 0.f, r_bwc = 0.f;
    if (tid < 176) r_bdh = g_B[B_bdh + tid];
    if (tid < 161) { r_bhr = g_B[B_bhr + tid]; r_bfr = g_B[B_bfr + tid]; r_bwc = g_B[B_bwc + tid]; }
    const float r_b1 = g_B[B_b1 + (int)rank * 352 + tid];
    const float r_b2 = g_B[B_b2 + (int)rank * 352 + tid];

    float lossAcc = 0.0f;
    __syncthreads();

    for (int t = 0; t < SEQB; t++) {
        const float lw = (rank == 0) ? g_inv_msum[t] : 0.0f;

        // P0: load x, m, d
        for (int i = tid; i < 8 * 164; i += NTHR) {
            int b = i / 164, f = i - b * 164;
            float xv = 0.f, mv = 0.f, dv = 0.f;
            if (f < 161) {
                int off = ((b0 + b) * SEQB + t) * FEAT + f;
                xv = values[off]; mv = masks[off]; dv = deltas[off];
            }
            sm->sX[b][f] = xv; sm->sM[b][f] = mv; sm->sD[b][f] = dv;
        }
        __syncthreads();

        // P1: Wdh partial gemv (K split 84/80), all 352 threads
        {
            int kh = tid / 176, row = tid - kh * 176;
            float acc[8] = {0,0,0,0,0,0,0,0};
            gemv_part8(acc, g_WT + O1, 176, row, &sm->sD[0][0], 164,
                       kh ? 84 : 0, kh ? 164 : 84);
#pragma unroll
            for (int b = 0; b < 8; b++) sm->sGate[b][kh * 176 + row] = acc[b];
        }
        __syncthreads();

        // P1b: combine -> decay h ; gamma_x (all threads)
        if (tid < 176) {
#pragma unroll
            for (int b = 0; b < 8; b++) {
                float gh = expf(-fmaxf(sm->sGate[b][tid] + sm->sGate[b][176 + tid] + r_bdh, 0.0f));
                sm->sH[b][tid] *= gh;
            }
        }
        for (int i = tid; i < 8 * 161; i += NTHR) {
            int b = i / 161, f = i - b * 161;
            sm->sGamX[b][f] = expf(-fmaxf(sm->sD[b][f] * g_B[B_wdx + f] + g_B[B_bdx + f], 0.0f));
        }
        __syncthreads();

        // P2: x_h partial (Whr^T, K=176 split 88/88)
        if (tid < 322) {
            int kh = tid / 161, row = tid - kh * 161;
            float acc[8] = {0,0,0,0,0,0,0,0};
            gemv_part8(acc, g_WT + O2, 164, row, &sm->sH[0][0], 176,
                       kh ? 88 : 0, kh ? 176 : 88);
#pragma unroll
            for (int b = 0; b < 8; b++) sm->sGate[b][kh * 176 + row] = acc[b];
        }
        __syncthreads();

        // P2b: combine x_h, loss, x_c
        if (tid < 161) {
#pragma unroll
            for (int b = 0; b < 8; b++) {
                float xh = sm->sGate[b][tid] + sm->sGate[b][176 + tid] + r_bhr;
                sm->sXh[b][tid] = xh;
                float x = sm->sX[b][tid], m = sm->sM[b][tid];
                lossAcc += fabsf(x - xh) * m * lw;
                sm->sD[b][tid] = m * x + (1.0f - m) * xh;   // x_c
            }
        }
        __syncthreads();

        // P3: z_h partial (Wfr, K=164 split 84/80)
        if (tid < 322) {
            int kh = tid / 161, row = tid - kh * 161;
            float acc[8] = {0,0,0,0,0,0,0,0};
            gemv_part8(acc, g_WT + O3, 164, row, &sm->sD[0][0], 164,
                       kh ? 84 : 0, kh ? 164 : 84);
#pragma unroll
            for (int b = 0; b < 8; b++) sm->sGate[b][kh * 176 + row] = acc[b];
        }
        __syncthreads();

        // P3b
        if (tid < 161) {
#pragma unroll
            for (int b = 0; b < 8; b++) {
                float zh = sm->sGate[b][tid] + sm->sGate[b][176 + tid] + r_bfr;
                sm->sZh[b][tid] = zh;
                lossAcc += fabsf(sm->sX[b][tid] - zh) * sm->sM[b][tid] * lw;
            }
        }
        __syncthreads();

        // P4: alpha partial (Wwc two K segments)
        if (tid < 322) {
            int seg = tid / 161, row = tid - seg * 161;
            float acc[8] = {0,0,0,0,0,0,0,0};
            if (seg == 0)
                gemv_part8(acc, g_WT + O4, 164, row, &sm->sGamX[0][0], 164, 0, 164);
            else
                gemv_part8(acc, g_WT + O4 + 164 * 164, 164, row, &sm->sM[0][0], 164, 0, 164);
#pragma unroll
            for (int b = 0; b < 8; b++) sm->sGate[b][seg * 176 + row] = acc[b];
        }
        __syncthreads();

        // P4b: c_h, loss, c_c, imputation store (batch split by rank)
        if (tid < 161) {
#pragma unroll
            for (int b = 0; b < 8; b++) {
                float alpha = sm->sGate[b][tid] + sm->sGate[b][176 + tid] + r_bwc;
                float ch = alpha * sm->sZh[b][tid] + (1.0f - alpha) * sm->sXh[b][tid];
                float x = sm->sX[b][tid], m = sm->sM[b][tid];
                lossAcc += fabsf(x - ch) * m * lw;
                float cc = m * x + (1.0f - m) * ch;
                sm->sXh[b][tid] = cc;  // reuse as c_c
                if ((b >> 2) == (int)rank)
                    out[513 + ((b0 + b) * SEQB + t) * FEAT + tid] = cc;
            }
        }
        __syncthreads();

        // fill1: pk = [c_c | m | h0]
        for (int i = tid; i < 504 * 8; i += NTHR) {
            int k = i >> 3, b = i & 7;
            float v = (k < 164) ? sm->sXh[b][k]
                   : (k < 328) ? sm->sM[b][k - 164]
                               : sm->sH0[b][k - 328];
            sm->pk[k][b] = v;
        }
        CSYNC();  // C1: all fill1 (last reads of old h0) done before any P6 remote write

        // P5: LSTM1 gates (row-split, f32x2)
        {
            unsigned long long acc[4] = {0ull, 0ull, 0ull, 0ull};
            gemv_big_f2(acc, g_WT + O5, (int)rank * 352 + tid, &sm->pk[0][0], 504);
#pragma unroll
            for (int bp = 0; bp < 4; bp++) {
                unsigned int lo, hi;
                asm("mov.b64 {%0, %1}, %2;" : "=r"(lo), "=r"(hi) : "l"(acc[bp]));
                sm->sGate[2 * bp][tid]     = __uint_as_float(lo) + r_b1;
                sm->sGate[2 * bp + 1][tid] = __uint_as_float(hi) + r_b1;
            }
        }
        __syncthreads();

        // P6: LSTM1 elementwise -> h0 (own half, write own + peer)
#pragma unroll
        for (int s = 0; s < 2; s++) {
            int item = tid + s * NTHR;
            int b = item / 88, jl = item - b * 88;
            float i_ = sigf(sm->sGate[b][jl]);
            float f_ = sigf(sm->sGate[b][88 + jl]);
            float g_ = tanhf(sm->sGate[b][176 + jl]);
            float o_ = sigf(sm->sGate[b][264 + jl]);
            float c = f_ * sm->sC0[b][jl] + i_ * g_;
            sm->sC0[b][jl] = c;
            float h0 = o_ * tanhf(c);
            int gj = (int)rank * 88 + jl;
            sm->sH0[b][gj] = h0;
            st_peer(&sm->sH0[b][gj], h0, peer);
        }
        CSYNC();  // C2: h0 halves visible everywhere

        // fill2: pk = [h0 | h]
        for (int i = tid; i < 352 * 8; i += NTHR) {
            int k = i >> 3, b = i & 7;
            float v = (k < 176) ? sm->sH0[b][k] : sm->sH[b][k - 176];
            sm->pk[k][b] = v;
        }
        CSYNC();  // C3: all fill2 (last reads of old h) done before any P8 remote write

        // P7: LSTM2 gates
        {
            unsigned long long acc[4] = {0ull, 0ull, 0ull, 0ull};
            gemv_big_f2(acc, g_WT + O6, (int)rank * 352 + tid, &sm->pk[0][0], 352);
#pragma unroll
            for (int bp = 0; bp < 4; bp++) {
                unsigned int lo, hi;
                asm("mov.b64 {%0, %1}, %2;" : "=r"(lo), "=r"(hi) : "l"(acc[bp]));
                sm->sGate[2 * bp][tid]     = __uint_as_float(lo) + r_b2;
                sm->sGate[2 * bp + 1][tid] = __uint_as_float(hi) + r_b2;
            }
        }
        __syncthreads();

        // P8: LSTM2 elementwise -> h (own half, write own + peer)
#pragma unroll
        for (int s = 0; s < 2; s++) {
            int item = tid + s * NTHR;
            int b = item / 88, jl = item - b * 88;
            float i_ = sigf(sm->sGate[b][jl]);
            float f_ = sigf(sm->sGate[b][88 + jl]);
            float g_ = tanhf(sm->sGate[b][176 + jl]);
            float o_ = sigf(sm->sGate[b][264 + jl]);
            float c = f_ * sm->sC[b][jl] + i_ * g_;
            sm->sC[b][jl] = c;
            float h = o_ * tanhf(c);
            int gj = (int)rank * 88 + jl;
            sm->sH[b][gj] = h;
            st_peer(&sm->sH[b][gj], h, peer);
        }
        CSYNC();  // C4: h halves visible before next step
    }

    // predictions (rank 0 handles all 8 batch elems of this cluster)
    if (rank == 0 && tid < 256) {
        int b = tid >> 5, lane = tid & 31;
        float s = 0.0f;
        for (int j = lane; j < 176; j += 32) s += sm->sH[b][j] * g_B[B_Wo + j];
        for (int o = 16; o; o >>= 1) s += __shfl_down_sync(0xffffffffu, s, o);
        if (lane == 0) out[1 + b0 + b] = sigf(s + g_B[B_bo]);
    }

    // loss partial (rank0 threads carry all loss)
    {
        float* lr = &sm->sGate[0][0];
        lr[tid] = lossAcc;
        __syncthreads();
        if (tid == 0 && rank == 0) {
            float s = 0.0f;
            for (int i = 0; i < NTHR; i++) s += lr[i];
            g_lossp[cid] = s;
        }
    }
}

__global__ void finalize_kernel(float* __restrict__ out)
{
    if (threadIdx.x == 0 && blockIdx.x == 0) {
        float s = 0.0f;
        for (int i = 0; i < NCLUS; i++) s += g_lossp[i];
        out[0] = s / (float)SEQB;
    }
}

extern "C" void kernel_launch(void* const* d_in, const int* in_sizes, int n_in,
                              void* d_out, int out_size)
{
    const float* values = (const float*)d_in[0];
    const float* masks  = (const float*)d_in[1];
    const float* deltas = (const float*)d_in[2];
    const float* Wdh  = (const float*)d_in[5];
    const float* bdh  = (const float*)d_in[6];
    const float* Wdx  = (const float*)d_in[7];
    const float* bdx  = (const float*)d_in[8];
    const float* Whr  = (const float*)d_in[9];
    const float* bhr  = (const float*)d_in[10];
    const float* Wfr  = (const float*)d_in[11];
    const float* bfr  = (const float*)d_in[12];
    const float* Wwc  = (const float*)d_in[13];
    const float* bwc  = (const float*)d_in[14];
    const float* Wih  = (const float*)d_in[15];
    const float* Whh  = (const float*)d_in[16];
    const float* bih  = (const float*)d_in[17];
    const float* bhh  = (const float*)d_in[18];
    const float* Wih2 = (const float*)d_in[19];
    const float* Whh2 = (const float*)d_in[20];
    const float* bih2 = (const float*)d_in[21];
    const float* bhh2 = (const float*)d_in[22];
    const float* Wo   = (const float*)d_in[23];
    const float* bo   = (const float*)d_in[24];
    float* out = (float*)d_out;

    cudaFuncSetAttribute(brits_kernel, cudaFuncAttributeMaxDynamicSharedMemorySize, SMEM_BYTES);

    repack_kernel<<<960, 256>>>(Wdh, Whr, Wfr, Wwc, Wih, Whh, Wih2, Whh2,
                                bdh, Wdx, bdx, bhr, bfr, bwc,
                                bih, bhh, bih2, bhh2, Wo, bo);
    msum_kernel<<<SEQB, 256>>>(masks);
    brits_kernel<<<NCTA, NTHR, SMEM_BYTES>>>(values, masks, deltas, out);
    finalize_kernel<<<1, 32>>>(out);
}

// round 5
// speedup vs baseline: 1.2389x; 1.1859x over previous
#include <cuda_runtime.h>

#define FEAT 161
#define HID  176
#define SEQB 456
#define NTHR 704
#define NCTA 128
#define NCLUS 64

// ---- float2-packed transposed weight offsets (float units) ----
// layout per region: float2 element (pair p, col c) at base + (p*Cp + c)*2
#define A1  0        // Wdh : 82 pairs, Cp=176
#define A2  28864    // Whr : 88 pairs, Cp=164
#define A3  57728    // Wfr : 82 pairs, Cp=164
#define A4  84624    // Wwc gx seg: 82 pairs, Cp=164
#define A4b 111520   // Wwc m  seg: 82 pairs, Cp=164
#define A5  138416   // LSTM1 cc seg: 82 pairs, Cp=704 (cols permuted)
#define A5m 253872   // LSTM1 m  seg: 82 pairs, Cp=704
#define A5h 369328   // LSTM1 h0 seg: 88 pairs, Cp=704
#define A6  493232   // LSTM2 h0 seg: 88 pairs, Cp=704
#define A6h 617136   // LSTM2 hd seg: 88 pairs, Cp=704
#define WT_TOTAL 741040

// ---- bias offsets ----
#define B_bdh 0
#define B_wdx 176
#define B_bdx 337
#define B_bhr 498
#define B_bfr 659
#define B_bwc 820
#define B_b1  981
#define B_b2  1685
#define B_Wo  2389
#define B_bo  2565
#define B_TOTAL 2566

#define SMEM_BYTES 103808

__device__ float g_WT[WT_TOTAL];
__device__ float g_B[B_TOTAL];
__device__ float g_inv_msum[SEQB];
__device__ float g_lossp[NCLUS];

// ============================= repack =====================================
__global__ void repack_kernel(
    const float* __restrict__ Wdh, const float* __restrict__ Whr,
    const float* __restrict__ Wfr, const float* __restrict__ Wwc,
    const float* __restrict__ Wih, const float* __restrict__ Whh,
    const float* __restrict__ Wih2, const float* __restrict__ Whh2,
    const float* __restrict__ bdh, const float* __restrict__ Wdx,
    const float* __restrict__ bdx, const float* __restrict__ bhr,
    const float* __restrict__ bfr, const float* __restrict__ bwc,
    const float* __restrict__ bih, const float* __restrict__ bhh,
    const float* __restrict__ bih2, const float* __restrict__ bhh2,
    const float* __restrict__ Wo, const float* __restrict__ bo)
{
    int stride = gridDim.x * blockDim.x;
    for (int idx = blockIdx.x * blockDim.x + threadIdx.x; idx < WT_TOTAL; idx += stride) {
        float v = 0.0f;
        int base, Cp, region;
        if      (idx < A2)  { base = A1;  Cp = 176; region = 0; }
        else if (idx < A3)  { base = A2;  Cp = 164; region = 1; }
        else if (idx < A4)  { base = A3;  Cp = 164; region = 2; }
        else if (idx < A4b) { base = A4;  Cp = 164; region = 3; }
        else if (idx < A5)  { base = A4b; Cp = 164; region = 4; }
        else if (idx < A5m) { base = A5;  Cp = 704; region = 5; }
        else if (idx < A5h) { base = A5m; Cp = 704; region = 6; }
        else if (idx < A6)  { base = A5h; Cp = 704; region = 7; }
        else if (idx < A6h) { base = A6;  Cp = 704; region = 8; }
        else                { base = A6h; Cp = 704; region = 9; }
        int j = idx - base, pc = j >> 1, half = j & 1;
        int p = pc / Cp, c = pc % Cp;
        int k = 2 * p + half;
        if (region >= 5) {
            // permuted LSTM column -> original gate row
            int rk = c / 352, rem = c % 352, q = rem / 88, jl = rem % 88;
            int r = q * 176 + rk * 88 + jl;
            switch (region) {
                case 5: if (k < 161) v = Wih[r * 322 + k]; break;
                case 6: if (k < 161) v = Wih[r * 322 + 161 + k]; break;
                case 7: v = Whh[r * 176 + k]; break;
                case 8: v = Wih2[r * 176 + k]; break;
                case 9: v = Whh2[r * 176 + k]; break;
            }
        } else {
            switch (region) {
                case 0: if (k < 161) v = Wdh[c * 161 + k]; break;
                case 1: if (c < 161) v = Whr[c * 176 + k]; break;
                case 2: if (c < 161 && k < 161 && k != c) v = Wfr[c * 161 + k]; break;
                case 3: if (c < 161 && k < 161) v = Wwc[c * 322 + k]; break;
                case 4: if (c < 161 && k < 161) v = Wwc[c * 322 + 161 + k]; break;
            }
        }
        g_WT[idx] = v;
    }
    for (int idx = blockIdx.x * blockDim.x + threadIdx.x; idx < B_TOTAL; idx += stride) {
        float v;
        if (idx < 176)        v = bdh[idx];
        else if (idx < 337)   { int f = idx - 176; v = Wdx[f * 161 + f]; }
        else if (idx < 498)   v = bdx[idx - 337];
        else if (idx < 659)   v = bhr[idx - 498];
        else if (idx < 820)   v = bfr[idx - 659];
        else if (idx < 981)   v = bwc[idx - 820];
        else if (idx < 1685)  {
            int j = idx - 981;
            int rk = j / 352, rem = j % 352, q = rem / 88, jl = rem % 88;
            int r = q * 176 + rk * 88 + jl;
            v = bih[r] + bhh[r];
        } else if (idx < 2389) {
            int j = idx - 1685;
            int rk = j / 352, rem = j % 352, q = rem / 88, jl = rem % 88;
            int r = q * 176 + rk * 88 + jl;
            v = bih2[r] + bhh2[r];
        }
        else if (idx < 2565)  v = Wo[idx - 2389];
        else                  v = bo[0];
        g_B[idx] = v;
    }
}

// ========================== msum precompute ===============================
__global__ void msum_kernel(const float* __restrict__ masks)
{
    __shared__ float red[256];
    int t = blockIdx.x;
    float s = 0.0f;
    for (int idx = threadIdx.x; idx < 512 * FEAT; idx += 256) {
        int b = idx / FEAT, f = idx - b * FEAT;
        s += masks[(b * SEQB + t) * FEAT + f];
    }
    red[threadIdx.x] = s;
    __syncthreads();
    for (int o = 128; o > 0; o >>= 1) {
        if (threadIdx.x < o) red[threadIdx.x] += red[threadIdx.x + o];
        __syncthreads();
    }
    if (threadIdx.x == 0) g_inv_msum[t] = 1.0f / (red[0] + 1e-5f);
}

// ========================== helpers =======================================
__device__ __forceinline__ float sigfast(float x)
{ return __fdividef(1.0f, 1.0f + __expf(-x)); }
__device__ __forceinline__ float tanhfast(float x)
{ return __fdividef(2.0f, 1.0f + __expf(-2.0f * x)) - 1.0f; }

__device__ __forceinline__ void st_peer(float* p, float v, int peer)
{
    unsigned int a = (unsigned int)__cvta_generic_to_shared(p);
    unsigned int ra;
    asm("mapa.shared::cluster.u32 %0, %1, %2;" : "=r"(ra) : "r"(a), "r"(peer));
    asm volatile("st.shared::cluster.f32 [%0], %1;" :: "r"(ra), "f"(v));
}

#define CSYNC() do { \
    asm volatile("barrier.cluster.arrive.aligned;" ::: "memory"); \
    asm volatile("barrier.cluster.wait.aligned;" ::: "memory"); } while (0)

#define FMA2(a, b, c) asm("fma.rn.f32x2 %0, %1, %2, %0;" : "+l"(a) : "l"(b), "l"(c))

// f32x2 GEMV over k-pair range [p0,p1): weights float2 [pair][Cp], input pk[k][8]
__device__ __forceinline__ void gemv8(unsigned long long acc[4],
                                      const float* __restrict__ wbase, int Cp, int col,
                                      const float* __restrict__ pk, int p0, int p1)
{
    const float2* wp = (const float2*)wbase + (size_t)p0 * Cp + col;
    const ulonglong2* ip = (const ulonglong2*)pk + 4 * p0;
#pragma unroll 4
    for (int p = p0; p < p1; p++) {
        float2 w = *wp; wp += Cp;
        ulonglong2 e0 = ip[0], e1 = ip[1], o0 = ip[2], o1 = ip[3]; ip += 4;
        unsigned long long wx, wy;
        asm("mov.b64 %0, {%1, %1};" : "=l"(wx) : "r"(__float_as_uint(w.x)));
        asm("mov.b64 %0, {%1, %1};" : "=l"(wy) : "r"(__float_as_uint(w.y)));
        FMA2(acc[0], wx, e0.x); FMA2(acc[1], wx, e0.y);
        FMA2(acc[2], wx, e1.x); FMA2(acc[3], wx, e1.y);
        FMA2(acc[0], wy, o0.x); FMA2(acc[1], wy, o0.y);
        FMA2(acc[2], wy, o1.x); FMA2(acc[3], wy, o1.y);
    }
}

// ========================== main persistent kernel ========================
struct __align__(16) SM {
    float d[164][8], m[164][8], x[164][8], gx[164][8];
    float xc[164][8], cc[164][8], xh[164][8], zh[164][8], al[164][8];
    float hd[176][8];
    float h0[2][176][8], hR[2][176][8];
    float c0[88][8], c1[88][8];
    float part[8][712];
};

__device__ __forceinline__ void store_part(SM* sm, int u, const unsigned long long acc[4])
{
#pragma unroll
    for (int bp = 0; bp < 4; bp++) {
        unsigned int lo, hi;
        asm("mov.b64 {%0, %1}, %2;" : "=r"(lo), "=r"(hi) : "l"(acc[bp]));
        sm->part[2 * bp][u]     = __uint_as_float(lo);
        sm->part[2 * bp + 1][u] = __uint_as_float(hi);
    }
}

__global__ void __launch_bounds__(NTHR, 1) __cluster_dims__(2, 1, 1)
brits_kernel(const float* __restrict__ values, const float* __restrict__ masks,
             const float* __restrict__ deltas, float* __restrict__ out)
{
    extern __shared__ char dynbuf[];
    SM* sm = (SM*)dynbuf;
    const int tid = threadIdx.x;
    unsigned int rank;
    asm("mov.u32 %0, %%cluster_ctarank;" : "=r"(rank));
    const int peer = (int)(rank ^ 1u);
    const int cid = blockIdx.x >> 1;
    const int b0 = cid * 8;

    // zero all shared state
    {
        float* sp = (float*)sm;
        for (int i = tid; i < SMEM_BYTES / 4; i += NTHR) sp[i] = 0.0f;
    }

    // prefetch slots: s0 = tid, s1 = tid + 704 (slots over 8b x 164f)
    const int s0 = tid,        b_0 = s0 / 164, f_0 = s0 % 164;
    const int s1 = tid + NTHR, b_1 = s1 / 164, f_1 = s1 % 164;
    const bool v0 = (f_0 < 161);
    const bool v1 = (s1 < 1312) && (f_1 < 161);
    float wdx0 = 0.f, bdx0 = 0.f, wdx1 = 0.f, bdx1 = 0.f;
    if (v0) { wdx0 = g_B[B_wdx + f_0]; bdx0 = g_B[B_bdx + f_0]; }
    if (v1) { wdx1 = g_B[B_wdx + f_1]; bdx1 = g_B[B_bdx + f_1]; }

    float px0 = 0.f, pm0 = 0.f, pd0 = 0.f, px1 = 0.f, pm1 = 0.f, pd1 = 0.f;
    if (v0) {
        int off = ((b0 + b_0) * SEQB + 0) * FEAT + f_0;
        px0 = values[off]; pm0 = masks[off]; pd0 = deltas[off];
    }
    if (v1) {
        int off = ((b0 + b_1) * SEQB + 0) * FEAT + f_1;
        px1 = values[off]; pm1 = masks[off]; pd1 = deltas[off];
    }

    // chunk bounds
    const int pb82[5] = {0, 21, 42, 62, 82};
    const int pb88[5] = {0, 22, 44, 66, 88};

    float lossAcc = 0.0f;
    __syncthreads();

    for (int t = 0; t < SEQB; t++) {
        const float lw = (rank == 0) ? g_inv_msum[t] : 0.0f;

        // P0: commit prefetched x/m/d(+gamma_x), issue next prefetch
        if (v0) {
            sm->x[f_0][b_0] = px0; sm->m[f_0][b_0] = pm0; sm->d[f_0][b_0] = pd0;
            sm->gx[f_0][b_0] = __expf(-fmaxf(pd0 * wdx0 + bdx0, 0.0f));
        }
        if (v1) {
            sm->x[f_1][b_1] = px1; sm->m[f_1][b_1] = pm1; sm->d[f_1][b_1] = pd1;
            sm->gx[f_1][b_1] = __expf(-fmaxf(pd1 * wdx1 + bdx1, 0.0f));
        }
        {
            int tn = (t + 1 < SEQB) ? t + 1 : SEQB - 1;
            if (v0) {
                int off = ((b0 + b_0) * SEQB + tn) * FEAT + f_0;
                px0 = values[off]; pm0 = masks[off]; pd0 = deltas[off];
            }
            if (v1) {
                int off = ((b0 + b_1) * SEQB + tn) * FEAT + f_1;
                px1 = values[off]; pm1 = masks[off]; pd1 = deltas[off];
            }
        }
        __syncthreads();

        // PA: Wdh gemv (176 rows x 4 k-chunks)
        {
            int kc = tid / 176, row = tid % 176;
            unsigned long long acc[4] = {0, 0, 0, 0};
            gemv8(acc, g_WT + A1, 176, row, &sm->d[0][0], pb82[kc], pb82[kc + 1]);
            store_part(sm, kc * 176 + row, acc);
        }
        __syncthreads();

        // PC1: gamma_h combine -> decayed h
        for (int u = tid; u < 1408; u += NTHR) {
            int j = u % 176, b = u / 176;
            float s = sm->part[b][j] + sm->part[b][176 + j]
                    + sm->part[b][352 + j] + sm->part[b][528 + j] + g_B[B_bdh + j];
            float gh = __expf(-fmaxf(s, 0.0f));
            sm->hd[j][b] = sm->hR[t & 1][j][b] * gh;
        }
        __syncthreads();

        // PB: Wwc gemv (161 rows x 4 chunks: 2 over gx, 2 over m)
        if (tid < 656) {
            int kc = tid / 164, row = tid % 164;
            if (row < 161) {
                unsigned long long acc[4] = {0, 0, 0, 0};
                if (kc < 2)
                    gemv8(acc, g_WT + A4,  164, row, &sm->gx[0][0], kc * 41, kc * 41 + 41);
                else
                    gemv8(acc, g_WT + A4b, 164, row, &sm->m[0][0], (kc - 2) * 41, (kc - 2) * 41 + 41);
                store_part(sm, kc * 164 + row, acc);
            }
        }
        __syncthreads();

        // PBc: alpha combine
        for (int u = tid; u < 1288; u += NTHR) {
            int f = u % 161, b = u / 161;
            sm->al[f][b] = sm->part[b][f] + sm->part[b][164 + f]
                         + sm->part[b][328 + f] + sm->part[b][492 + f] + g_B[B_bwc + f];
        }
        __syncthreads();

        // P2: Whr gemv (input hd, 88 pairs x 4 chunks)
        if (tid < 656) {
            int kc = tid / 164, row = tid % 164;
            if (row < 161) {
                unsigned long long acc[4] = {0, 0, 0, 0};
                gemv8(acc, g_WT + A2, 164, row, &sm->hd[0][0], pb88[kc], pb88[kc + 1]);
                store_part(sm, kc * 164 + row, acc);
            }
        }
        __syncthreads();

        // P2b: x_h, loss1, x_c
        for (int u = tid; u < 1288; u += NTHR) {
            int f = u % 161, b = u / 161;
            float xh = sm->part[b][f] + sm->part[b][164 + f]
                     + sm->part[b][328 + f] + sm->part[b][492 + f] + g_B[B_bhr + f];
            float x = sm->x[f][b], m = sm->m[f][b];
            lossAcc += fabsf(x - xh) * m * lw;
            sm->xh[f][b] = xh;
            sm->xc[f][b] = m * x + (1.0f - m) * xh;
        }
        __syncthreads();

        // P3: Wfr gemv (input xc)
        if (tid < 656) {
            int kc = tid / 164, row = tid % 164;
            if (row < 161) {
                unsigned long long acc[4] = {0, 0, 0, 0};
                gemv8(acc, g_WT + A3, 164, row, &sm->xc[0][0], pb82[kc], pb82[kc + 1]);
                store_part(sm, kc * 164 + row, acc);
            }
        }
        __syncthreads();

        // P3b: z_h, loss2
        for (int u = tid; u < 1288; u += NTHR) {
            int f = u % 161, b = u / 161;
            float zh = sm->part[b][f] + sm->part[b][164 + f]
                     + sm->part[b][328 + f] + sm->part[b][492 + f] + g_B[B_bfr + f];
            sm->zh[f][b] = zh;
            lossAcc += fabsf(sm->x[f][b] - zh) * sm->m[f][b] * lw;
        }
        __syncthreads();

        // P4b: c_h, loss3, c_c + imputation store
        for (int u = tid; u < 1288; u += NTHR) {
            int f = u % 161, b = u / 161;
            float al = sm->al[f][b];
            float xh = sm->xh[f][b];
            float ch = xh + al * (sm->zh[f][b] - xh);
            float x = sm->x[f][b], m = sm->m[f][b];
            lossAcc += fabsf(x - ch) * m * lw;
            float cc = m * x + (1.0f - m) * ch;
            sm->cc[f][b] = cc;
            if ((b >> 2) == (int)rank)
                out[513 + ((b0 + b) * SEQB + t) * FEAT + f] = cc;
        }
        __syncthreads();

        // P5: LSTM1 gates (352 local rows x 2 k-chunks)
        {
            int kh = tid / 352, lrow = tid % 352;
            int col = (int)rank * 352 + lrow;
            unsigned long long acc[4] = {0, 0, 0, 0};
            if (kh == 0) {
                gemv8(acc, g_WT + A5,  704, col, &sm->cc[0][0], 0, 82);
                gemv8(acc, g_WT + A5m, 704, col, &sm->m[0][0],  0, 44);
            } else {
                gemv8(acc, g_WT + A5m, 704, col, &sm->m[0][0], 44, 82);
                gemv8(acc, g_WT + A5h, 704, col, &sm->h0[t & 1][0][0], 0, 88);
            }
            store_part(sm, kh * 352 + lrow, acc);
        }
        __syncthreads();

        // P6: LSTM1 elementwise -> h0 new (own half, local + peer store)
        {
            int jl = tid % 88, b = tid / 88;
            float g0 = sm->part[b][jl]       + sm->part[b][352 + jl]       + g_B[B_b1 + (int)rank * 352 + jl];
            float g1 = sm->part[b][88 + jl]  + sm->part[b][352 + 88 + jl]  + g_B[B_b1 + (int)rank * 352 + 88 + jl];
            float g2 = sm->part[b][176 + jl] + sm->part[b][352 + 176 + jl] + g_B[B_b1 + (int)rank * 352 + 176 + jl];
            float g3 = sm->part[b][264 + jl] + sm->part[b][352 + 264 + jl] + g_B[B_b1 + (int)rank * 352 + 264 + jl];
            float i_ = sigfast(g0), f_ = sigfast(g1), gg = tanhfast(g2), o_ = sigfast(g3);
            float c = f_ * sm->c0[jl][b] + i_ * gg;
            sm->c0[jl][b] = c;
            float h0v = o_ * tanhfast(c);
            int idx = (int)rank * 88 + jl;
            sm->h0[(t + 1) & 1][idx][b] = h0v;
            st_peer(&sm->h0[(t + 1) & 1][idx][b], h0v, peer);
        }
        CSYNC();

        // P7: LSTM2 gates
        {
            int kh = tid / 352, lrow = tid % 352;
            int col = (int)rank * 352 + lrow;
            unsigned long long acc[4] = {0, 0, 0, 0};
            if (kh == 0)
                gemv8(acc, g_WT + A6,  704, col, &sm->h0[(t + 1) & 1][0][0], 0, 88);
            else
                gemv8(acc, g_WT + A6h, 704, col, &sm->hd[0][0], 0, 88);
            store_part(sm, kh * 352 + lrow, acc);
        }
        __syncthreads();

        // P8: LSTM2 elementwise -> h new (own half, local + peer store)
        {
            int jl = tid % 88, b = tid / 88;
            float g0 = sm->part[b][jl]       + sm->part[b][352 + jl]       + g_B[B_b2 + (int)rank * 352 + jl];
            float g1 = sm->part[b][88 + jl]  + sm->part[b][352 + 88 + jl]  + g_B[B_b2 + (int)rank * 352 + 88 + jl];
            float g2 = sm->part[b][176 + jl] + sm->part[b][352 + 176 + jl] + g_B[B_b2 + (int)rank * 352 + 176 + jl];
            float g3 = sm->part[b][264 + jl] + sm->part[b][352 + 264 + jl] + g_B[B_b2 + (int)rank * 352 + 264 + jl];
            float i_ = sigfast(g0), f_ = sigfast(g1), gg = tanhfast(g2), o_ = sigfast(g3);
            float c = f_ * sm->c1[jl][b] + i_ * gg;
            sm->c1[jl][b] = c;
            float hv = o_ * tanhfast(c);
            int idx = (int)rank * 88 + jl;
            sm->hR[(t + 1) & 1][idx][b] = hv;
            st_peer(&sm->hR[(t + 1) & 1][idx][b], hv, peer);
        }
        CSYNC();
    }

    // predictions: final h is in hR[SEQB & 1] == hR[0]
    if (rank == 0 && tid < 256) {
        int b = tid >> 5, lane = tid & 31;
        float s = 0.0f;
        for (int j = lane; j < 176; j += 32) s += sm->hR[0][j][b] * g_B[B_Wo + j];
        for (int o = 16; o; o >>= 1) s += __shfl_down_sync(0xffffffffu, s, o);
        if (lane == 0) out[1 + b0 + b] = sigfast(s + g_B[B_bo]);
    }

    // loss partial
    {
        float* lr = &sm->part[0][0];
        lr[tid] = lossAcc;
        __syncthreads();
        if (tid == 0 && rank == 0) {
            float s = 0.0f;
            for (int i = 0; i < NTHR; i++) s += lr[i];
            g_lossp[cid] = s;
        }
    }
}

__global__ void finalize_kernel(float* __restrict__ out)
{
    if (threadIdx.x == 0 && blockIdx.x == 0) {
        float s = 0.0f;
        for (int i = 0; i < NCLUS; i++) s += g_lossp[i];
        out[0] = s / (float)SEQB;
    }
}

extern "C" void kernel_launch(void* const* d_in, const int* in_sizes, int n_in,
                              void* d_out, int out_size)
{
    const float* values = (const float*)d_in[0];
    const float* masks  = (const float*)d_in[1];
    const float* deltas = (const float*)d_in[2];
    const float* Wdh  = (const float*)d_in[5];
    const float* bdh  = (const float*)d_in[6];
    const float* Wdx  = (const float*)d_in[7];
    const float* bdx  = (const float*)d_in[8];
    const float* Whr  = (const float*)d_in[9];
    const float* bhr  = (const float*)d_in[10];
    const float* Wfr  = (const float*)d_in[11];
    const float* bfr  = (const float*)d_in[12];
    const float* Wwc  = (const float*)d_in[13];
    const float* bwc  = (const float*)d_in[14];
    const float* Wih  = (const float*)d_in[15];
    const float* Whh  = (const float*)d_in[16];
    const float* bih  = (const float*)d_in[17];
    const float* bhh  = (const float*)d_in[18];
    const float* Wih2 = (const float*)d_in[19];
    const float* Whh2 = (const float*)d_in[20];
    const float* bih2 = (const float*)d_in[21];
    const float* bhh2 = (const float*)d_in[22];
    const float* Wo   = (const float*)d_in[23];
    const float* bo   = (const float*)d_in[24];
    float* out = (float*)d_out;

    cudaFuncSetAttribute(brits_kernel, cudaFuncAttributeMaxDynamicSharedMemorySize, SMEM_BYTES);

    repack_kernel<<<960, 256>>>(Wdh, Whr, Wfr, Wwc, Wih, Whh, Wih2, Whh2,
                                bdh, Wdx, bdx, bhr, bfr, bwc,
                                bih, bhh, bih2, bhh2, Wo, bo);
    msum_kernel<<<SEQB, 256>>>(masks);
    brits_kernel<<<NCTA, NTHR, SMEM_BYTES>>>(values, masks, deltas, out);
    finalize_kernel<<<1, 32>>>(out);
}

// round 6
// speedup vs baseline: 1.2392x; 1.0002x over previous
#include <cuda_runtime.h>

#define FEAT 161
#define HID  176
#define SEQB 456
#define NTHR 704
#define NCTA 128
#define NCLUS 64

// ---- float2-packed transposed weight offsets (float units) ----
// layout per region: float2 element (pair p, col c) at base + (p*Cp + c)*2
#define A1  0        // Wdh : 82 pairs, Cp=176
#define A2  28864    // Whr : 88 pairs, Cp=164
#define A3  57728    // Wfr : 82 pairs, Cp=164
#define A4  84624    // Wwc gx seg: 82 pairs, Cp=164
#define A4b 111520   // Wwc m  seg: 82 pairs, Cp=164
#define A5  138416   // LSTM1 cc seg: 82 pairs, Cp=704 (cols permuted)
#define A5m 253872   // LSTM1 m  seg: 82 pairs, Cp=704
#define A5h 369328   // LSTM1 h0 seg: 88 pairs, Cp=704
#define A6  493232   // LSTM2 h0 seg: 88 pairs, Cp=704
#define A6h 617136   // LSTM2 hd seg: 88 pairs, Cp=704
#define WT_TOTAL 741040

// ---- bias offsets ----
#define B_bdh 0
#define B_wdx 176
#define B_bdx 337
#define B_bhr 498
#define B_bfr 659
#define B_bwc 820
#define B_b1  981
#define B_b2  1685
#define B_Wo  2389
#define B_bo  2565
#define B_TOTAL 2566

#define SMEM_BYTES 103808

__device__ float g_WT[WT_TOTAL];
__device__ float g_B[B_TOTAL];
__device__ float g_inv_msum[SEQB];
__device__ float g_lossp[NCLUS];

// ============================= repack =====================================
__global__ void repack_kernel(
    const float* __restrict__ Wdh, const float* __restrict__ Whr,
    const float* __restrict__ Wfr, const float* __restrict__ Wwc,
    const float* __restrict__ Wih, const float* __restrict__ Whh,
    const float* __restrict__ Wih2, const float* __restrict__ Whh2,
    const float* __restrict__ bdh, const float* __restrict__ Wdx,
    const float* __restrict__ bdx, const float* __restrict__ bhr,
    const float* __restrict__ bfr, const float* __restrict__ bwc,
    const float* __restrict__ bih, const float* __restrict__ bhh,
    const float* __restrict__ bih2, const float* __restrict__ bhh2,
    const float* __restrict__ Wo, const float* __restrict__ bo)
{
    int stride = gridDim.x * blockDim.x;
    for (int idx = blockIdx.x * blockDim.x + threadIdx.x; idx < WT_TOTAL; idx += stride) {
        float v = 0.0f;
        int base, Cp, region;
        if      (idx < A2)  { base = A1;  Cp = 176; region = 0; }
        else if (idx < A3)  { base = A2;  Cp = 164; region = 1; }
        else if (idx < A4)  { base = A3;  Cp = 164; region = 2; }
        else if (idx < A4b) { base = A4;  Cp = 164; region = 3; }
        else if (idx < A5)  { base = A4b; Cp = 164; region = 4; }
        else if (idx < A5m) { base = A5;  Cp = 704; region = 5; }
        else if (idx < A5h) { base = A5m; Cp = 704; region = 6; }
        else if (idx < A6)  { base = A5h; Cp = 704; region = 7; }
        else if (idx < A6h) { base = A6;  Cp = 704; region = 8; }
        else                { base = A6h; Cp = 704; region = 9; }
        int j = idx - base, pc = j >> 1, half = j & 1;
        int p = pc / Cp, c = pc % Cp;
        int k = 2 * p + half;
        if (region >= 5) {
            // permuted LSTM column -> original gate row
            int rk = c / 352, rem = c % 352, q = rem / 88, jl = rem % 88;
            int r = q * 176 + rk * 88 + jl;
            switch (region) {
                case 5: if (k < 161) v = Wih[r * 322 + k]; break;
                case 6: if (k < 161) v = Wih[r * 322 + 161 + k]; break;
                case 7: v = Whh[r * 176 + k]; break;
                case 8: v = Wih2[r * 176 + k]; break;
                case 9: v = Whh2[r * 176 + k]; break;
            }
        } else {
            switch (region) {
                case 0: if (k < 161) v = Wdh[c * 161 + k]; break;
                case 1: if (c < 161) v = Whr[c * 176 + k]; break;
                case 2: if (c < 161 && k < 161 && k != c) v = Wfr[c * 161 + k]; break;
                case 3: if (c < 161 && k < 161) v = Wwc[c * 322 + k]; break;
                case 4: if (c < 161 && k < 161) v = Wwc[c * 322 + 161 + k]; break;
            }
        }
        g_WT[idx] = v;
    }
    for (int idx = blockIdx.x * blockDim.x + threadIdx.x; idx < B_TOTAL; idx += stride) {
        float v;
        if (idx < 176)        v = bdh[idx];
        else if (idx < 337)   { int f = idx - 176; v = Wdx[f * 161 + f]; }
        else if (idx < 498)   v = bdx[idx - 337];
        else if (idx < 659)   v = bhr[idx - 498];
        else if (idx < 820)   v = bfr[idx - 659];
        else if (idx < 981)   v = bwc[idx - 820];
        else if (idx < 1685)  {
            int j = idx - 981;
            int rk = j / 352, rem = j % 352, q = rem / 88, jl = rem % 88;
            int r = q * 176 + rk * 88 + jl;
            v = bih[r] + bhh[r];
        } else if (idx < 2389) {
            int j = idx - 1685;
            int rk = j / 352, rem = j % 352, q = rem / 88, jl = rem % 88;
            int r = q * 176 + rk * 88 + jl;
            v = bih2[r] + bhh2[r];
        }
        else if (idx < 2565)  v = Wo[idx - 2389];
        else                  v = bo[0];
        g_B[idx] = v;
    }
}

// ========================== msum precompute ===============================
__global__ void msum_kernel(const float* __restrict__ masks)
{
    __shared__ float red[256];
    int t = blockIdx.x;
    float s = 0.0f;
    for (int idx = threadIdx.x; idx < 512 * FEAT; idx += 256) {
        int b = idx / FEAT, f = idx - b * FEAT;
        s += masks[(b * SEQB + t) * FEAT + f];
    }
    red[threadIdx.x] = s;
    __syncthreads();
    for (int o = 128; o > 0; o >>= 1) {
        if (threadIdx.x < o) red[threadIdx.x] += red[threadIdx.x + o];
        __syncthreads();
    }
    if (threadIdx.x == 0) g_inv_msum[t] = 1.0f / (red[0] + 1e-5f);
}

// ========================== helpers =======================================
__device__ __forceinline__ float sigfast(float x)
{ return __fdividef(1.0f, 1.0f + __expf(-x)); }
__device__ __forceinline__ float tanhfast(float x)
{ return __fdividef(2.0f, 1.0f + __expf(-2.0f * x)) - 1.0f; }

__device__ __forceinline__ void st_peer(float* p, float v, int peer)
{
    unsigned int a = (unsigned int)__cvta_generic_to_shared(p);
    unsigned int ra;
    asm("mapa.shared::cluster.u32 %0, %1, %2;" : "=r"(ra) : "r"(a), "r"(peer));
    asm volatile("st.shared::cluster.f32 [%0], %1;" :: "r"(ra), "f"(v));
}

#define CSYNC() do { \
    asm volatile("barrier.cluster.arrive.aligned;" ::: "memory"); \
    asm volatile("barrier.cluster.wait.aligned;" ::: "memory"); } while (0)

#define FMA2(a, b, c) asm("fma.rn.f32x2 %0, %1, %2, %0;" : "+l"(a) : "l"(b), "l"(c))

// f32x2 GEMV over k-pair range [p0,p1): weights float2 [pair][Cp], input pk[k][8]
__device__ __forceinline__ void gemv8(unsigned long long acc[4],
                                      const float* __restrict__ wbase, int Cp, int col,
                                      const float* __restrict__ pk, int p0, int p1)
{
    const float2* wp = (const float2*)wbase + (size_t)p0 * Cp + col;
    const ulonglong2* ip = (const ulonglong2*)pk + 4 * p0;
#pragma unroll 4
    for (int p = p0; p < p1; p++) {
        float2 w = *wp; wp += Cp;
        ulonglong2 e0 = ip[0], e1 = ip[1], o0 = ip[2], o1 = ip[3]; ip += 4;
        unsigned long long wx, wy;
        asm("mov.b64 %0, {%1, %1};" : "=l"(wx) : "r"(__float_as_uint(w.x)));
        asm("mov.b64 %0, {%1, %1};" : "=l"(wy) : "r"(__float_as_uint(w.y)));
        FMA2(acc[0], wx, e0.x); FMA2(acc[1], wx, e0.y);
        FMA2(acc[2], wx, e1.x); FMA2(acc[3], wx, e1.y);
        FMA2(acc[0], wy, o0.x); FMA2(acc[1], wy, o0.y);
        FMA2(acc[2], wy, o1.x); FMA2(acc[3], wy, o1.y);
    }
}

// ========================== main persistent kernel ========================
struct __align__(16) SM {
    float d[164][8], m[164][8], x[164][8], gx[164][8];
    float xc[164][8], cc[164][8], xh[164][8], zh[164][8], al[164][8];
    float hd[176][8];
    float h0[2][176][8], hR[2][176][8];
    float c0[88][8], c1[88][8];
    float part[8][712];
};

__device__ __forceinline__ void store_part(SM* sm, int u, const unsigned long long acc[4])
{
#pragma unroll
    for (int bp = 0; bp < 4; bp++) {
        unsigned int lo, hi;
        asm("mov.b64 {%0, %1}, %2;" : "=r"(lo), "=r"(hi) : "l"(acc[bp]));
        sm->part[2 * bp][u]     = __uint_as_float(lo);
        sm->part[2 * bp + 1][u] = __uint_as_float(hi);
    }
}

__global__ void __launch_bounds__(NTHR, 1) __cluster_dims__(2, 1, 1)
brits_kernel(const float* __restrict__ values, const float* __restrict__ masks,
             const float* __restrict__ deltas, float* __restrict__ out)
{
    extern __shared__ char dynbuf[];
    SM* sm = (SM*)dynbuf;
    const int tid = threadIdx.x;
    unsigned int rank;
    asm("mov.u32 %0, %%cluster_ctarank;" : "=r"(rank));
    const int peer = (int)(rank ^ 1u);
    const int cid = blockIdx.x >> 1;
    const int b0 = cid * 8;

    // zero all shared state
    {
        float* sp = (float*)sm;
        for (int i = tid; i < SMEM_BYTES / 4; i += NTHR) sp[i] = 0.0f;
    }

    // prefetch slots: s0 = tid, s1 = tid + 704 (slots over 8b x 164f)
    const int s0 = tid,        b_0 = s0 / 164, f_0 = s0 % 164;
    const int s1 = tid + NTHR, b_1 = s1 / 164, f_1 = s1 % 164;
    const bool v0 = (f_0 < 161);
    const bool v1 = (s1 < 1312) && (f_1 < 161);
    float wdx0 = 0.f, bdx0 = 0.f, wdx1 = 0.f, bdx1 = 0.f;
    if (v0) { wdx0 = g_B[B_wdx + f_0]; bdx0 = g_B[B_bdx + f_0]; }
    if (v1) { wdx1 = g_B[B_wdx + f_1]; bdx1 = g_B[B_bdx + f_1]; }

    float px0 = 0.f, pm0 = 0.f, pd0 = 0.f, px1 = 0.f, pm1 = 0.f, pd1 = 0.f;
    if (v0) {
        int off = ((b0 + b_0) * SEQB + 0) * FEAT + f_0;
        px0 = values[off]; pm0 = masks[off]; pd0 = deltas[off];
    }
    if (v1) {
        int off = ((b0 + b_1) * SEQB + 0) * FEAT + f_1;
        px1 = values[off]; pm1 = masks[off]; pd1 = deltas[off];
    }

    // chunk bounds
    const int pb82[5] = {0, 21, 42, 62, 82};
    const int pb88[5] = {0, 22, 44, 66, 88};

    float lossAcc = 0.0f;
    __syncthreads();

    for (int t = 0; t < SEQB; t++) {
        const float lw = (rank == 0) ? g_inv_msum[t] : 0.0f;

        // P0: commit prefetched x/m/d(+gamma_x), issue next prefetch
        if (v0) {
            sm->x[f_0][b_0] = px0; sm->m[f_0][b_0] = pm0; sm->d[f_0][b_0] = pd0;
            sm->gx[f_0][b_0] = __expf(-fmaxf(pd0 * wdx0 + bdx0, 0.0f));
        }
        if (v1) {
            sm->x[f_1][b_1] = px1; sm->m[f_1][b_1] = pm1; sm->d[f_1][b_1] = pd1;
            sm->gx[f_1][b_1] = __expf(-fmaxf(pd1 * wdx1 + bdx1, 0.0f));
        }
        {
            int tn = (t + 1 < SEQB) ? t + 1 : SEQB - 1;
            if (v0) {
                int off = ((b0 + b_0) * SEQB + tn) * FEAT + f_0;
                px0 = values[off]; pm0 = masks[off]; pd0 = deltas[off];
            }
            if (v1) {
                int off = ((b0 + b_1) * SEQB + tn) * FEAT + f_1;
                px1 = values[off]; pm1 = masks[off]; pd1 = deltas[off];
            }
        }
        __syncthreads();

        // PA: Wdh gemv (176 rows x 4 k-chunks)
        {
            int kc = tid / 176, row = tid % 176;
            unsigned long long acc[4] = {0, 0, 0, 0};
            gemv8(acc, g_WT + A1, 176, row, &sm->d[0][0], pb82[kc], pb82[kc + 1]);
            store_part(sm, kc * 176 + row, acc);
        }
        __syncthreads();

        // PC1: gamma_h combine -> decayed h
        for (int u = tid; u < 1408; u += NTHR) {
            int j = u % 176, b = u / 176;
            float s = sm->part[b][j] + sm->part[b][176 + j]
                    + sm->part[b][352 + j] + sm->part[b][528 + j] + g_B[B_bdh + j];
            float gh = __expf(-fmaxf(s, 0.0f));
            sm->hd[j][b] = sm->hR[t & 1][j][b] * gh;
        }
        __syncthreads();

        // PB: Wwc gemv (161 rows x 4 chunks: 2 over gx, 2 over m)
        if (tid < 656) {
            int kc = tid / 164, row = tid % 164;
            if (row < 161) {
                unsigned long long acc[4] = {0, 0, 0, 0};
                if (kc < 2)
                    gemv8(acc, g_WT + A4,  164, row, &sm->gx[0][0], kc * 41, kc * 41 + 41);
                else
                    gemv8(acc, g_WT + A4b, 164, row, &sm->m[0][0], (kc - 2) * 41, (kc - 2) * 41 + 41);
                store_part(sm, kc * 164 + row, acc);
            }
        }
        __syncthreads();

        // PBc: alpha combine
        for (int u = tid; u < 1288; u += NTHR) {
            int f = u % 161, b = u / 161;
            sm->al[f][b] = sm->part[b][f] + sm->part[b][164 + f]
                         + sm->part[b][328 + f] + sm->part[b][492 + f] + g_B[B_bwc + f];
        }
        __syncthreads();

        // P2: Whr gemv (input hd, 88 pairs x 4 chunks)
        if (tid < 656) {
            int kc = tid / 164, row = tid % 164;
            if (row < 161) {
                unsigned long long acc[4] = {0, 0, 0, 0};
                gemv8(acc, g_WT + A2, 164, row, &sm->hd[0][0], pb88[kc], pb88[kc + 1]);
                store_part(sm, kc * 164 + row, acc);
            }
        }
        __syncthreads();

        // P2b: x_h, loss1, x_c
        for (int u = tid; u < 1288; u += NTHR) {
            int f = u % 161, b = u / 161;
            float xh = sm->part[b][f] + sm->part[b][164 + f]
                     + sm->part[b][328 + f] + sm->part[b][492 + f] + g_B[B_bhr + f];
            float x = sm->x[f][b], m = sm->m[f][b];
            lossAcc += fabsf(x - xh) * m * lw;
            sm->xh[f][b] = xh;
            sm->xc[f][b] = m * x + (1.0f - m) * xh;
        }
        __syncthreads();

        // P3: Wfr gemv (input xc)
        if (tid < 656) {
            int kc = tid / 164, row = tid % 164;
            if (row < 161) {
                unsigned long long acc[4] = {0, 0, 0, 0};
                gemv8(acc, g_WT + A3, 164, row, &sm->xc[0][0], pb82[kc], pb82[kc + 1]);
                store_part(sm, kc * 164 + row, acc);
            }
        }
        __syncthreads();

        // P3b: z_h, loss2
        for (int u = tid; u < 1288; u += NTHR) {
            int f = u % 161, b = u / 161;
            float zh = sm->part[b][f] + sm->part[b][164 + f]
                     + sm->part[b][328 + f] + sm->part[b][492 + f] + g_B[B_bfr + f];
            sm->zh[f][b] = zh;
            lossAcc += fabsf(sm->x[f][b] - zh) * sm->m[f][b] * lw;
        }
        __syncthreads();

        // P4b: c_h, loss3, c_c + imputation store
        for (int u = tid; u < 1288; u += NTHR) {
            int f = u % 161, b = u / 161;
            float al = sm->al[f][b];
            float xh = sm->xh[f][b];
            float ch = xh + al * (sm->zh[f][b] - xh);
            float x = sm->x[f][b], m = sm->m[f][b];
            lossAcc += fabsf(x - ch) * m * lw;
            float cc = m * x + (1.0f - m) * ch;
            sm->cc[f][b] = cc;
            if ((b >> 2) == (int)rank)
                out[513 + ((b0 + b) * SEQB + t) * FEAT + f] = cc;
        }
        __syncthreads();

        // P5: LSTM1 gates (352 local rows x 2 k-chunks)
        {
            int kh = tid / 352, lrow = tid % 352;
            int col = (int)rank * 352 + lrow;
            unsigned long long acc[4] = {0, 0, 0, 0};
            if (kh == 0) {
                gemv8(acc, g_WT + A5,  704, col, &sm->cc[0][0], 0, 82);
                gemv8(acc, g_WT + A5m, 704, col, &sm->m[0][0],  0, 44);
            } else {
                gemv8(acc, g_WT + A5m, 704, col, &sm->m[0][0], 44, 82);
                gemv8(acc, g_WT + A5h, 704, col, &sm->h0[t & 1][0][0], 0, 88);
            }
            store_part(sm, kh * 352 + lrow, acc);
        }
        __syncthreads();

        // P6: LSTM1 elementwise -> h0 new (own half, local + peer store)
        {
            int jl = tid % 88, b = tid / 88;
            float g0 = sm->part[b][jl]       + sm->part[b][352 + jl]       + g_B[B_b1 + (int)rank * 352 + jl];
            float g1 = sm->part[b][88 + jl]  + sm->part[b][352 + 88 + jl]  + g_B[B_b1 + (int)rank * 352 + 88 + jl];
            float g2 = sm->part[b][176 + jl] + sm->part[b][352 + 176 + jl] + g_B[B_b1 + (int)rank * 352 + 176 + jl];
            float g3 = sm->part[b][264 + jl] + sm->part[b][352 + 264 + jl] + g_B[B_b1 + (int)rank * 352 + 264 + jl];
            float i_ = sigfast(g0), f_ = sigfast(g1), gg = tanhfast(g2), o_ = sigfast(g3);
            float c = f_ * sm->c0[jl][b] + i_ * gg;
            sm->c0[jl][b] = c;
            float h0v = o_ * tanhfast(c);
            int idx = (int)rank * 88 + jl;
            sm->h0[(t + 1) & 1][idx][b] = h0v;
            st_peer(&sm->h0[(t + 1) & 1][idx][b], h0v, peer);
        }
        CSYNC();

        // P7: LSTM2 gates
        {
            int kh = tid / 352, lrow = tid % 352;
            int col = (int)rank * 352 + lrow;
            unsigned long long acc[4] = {0, 0, 0, 0};
            if (kh == 0)
                gemv8(acc, g_WT + A6,  704, col, &sm->h0[(t + 1) & 1][0][0], 0, 88);
            else
                gemv8(acc, g_WT + A6h, 704, col, &sm->hd[0][0], 0, 88);
            store_part(sm, kh * 352 + lrow, acc);
        }
        __syncthreads();

        // P8: LSTM2 elementwise -> h new (own half, local + peer store)
        {
            int jl = tid % 88, b = tid / 88;
            float g0 = sm->part[b][jl]       + sm->part[b][352 + jl]       + g_B[B_b2 + (int)rank * 352 + jl];
            float g1 = sm->part[b][88 + jl]  + sm->part[b][352 + 88 + jl]  + g_B[B_b2 + (int)rank * 352 + 88 + jl];
            float g2 = sm->part[b][176 + jl] + sm->part[b][352 + 176 + jl] + g_B[B_b2 + (int)rank * 352 + 176 + jl];
            float g3 = sm->part[b][264 + jl] + sm->part[b][352 + 264 + jl] + g_B[B_b2 + (int)rank * 352 + 264 + jl];
            float i_ = sigfast(g0), f_ = sigfast(g1), gg = tanhfast(g2), o_ = sigfast(g3);
            float c = f_ * sm->c1[jl][b] + i_ * gg;
            sm->c1[jl][b] = c;
            float hv = o_ * tanhfast(c);
            int idx = (int)rank * 88 + jl;
            sm->hR[(t + 1) & 1][idx][b] = hv;
            st_peer(&sm->hR[(t + 1) & 1][idx][b], hv, peer);
        }
        CSYNC();
    }

    // predictions: final h is in hR[SEQB & 1] == hR[0]
    if (rank == 0 && tid < 256) {
        int b = tid >> 5, lane = tid & 31;
        float s = 0.0f;
        for (int j = lane; j < 176; j += 32) s += sm->hR[0][j][b] * g_B[B_Wo + j];
        for (int o = 16; o; o >>= 1) s += __shfl_down_sync(0xffffffffu, s, o);
        if (lane == 0) out[1 + b0 + b] = sigfast(s + g_B[B_bo]);
    }

    // loss partial
    {
        float* lr = &sm->part[0][0];
        lr[tid] = lossAcc;
        __syncthreads();
        if (tid == 0 && rank == 0) {
            float s = 0.0f;
            for (int i = 0; i < NTHR; i++) s += lr[i];
            g_lossp[cid] = s;
        }
    }
}

__global__ void finalize_kernel(float* __restrict__ out)
{
    if (threadIdx.x == 0 && blockIdx.x == 0) {
        float s = 0.0f;
        for (int i = 0; i < NCLUS; i++) s += g_lossp[i];
        out[0] = s / (float)SEQB;
    }
}

extern "C" void kernel_launch(void* const* d_in, const int* in_sizes, int n_in,
                              void* d_out, int out_size)
{
    const float* values = (const float*)d_in[0];
    const float* masks  = (const float*)d_in[1];
    const float* deltas = (const float*)d_in[2];
    const float* Wdh  = (const float*)d_in[5];
    const float* bdh  = (const float*)d_in[6];
    const float* Wdx  = (const float*)d_in[7];
    const float* bdx  = (const float*)d_in[8];
    const float* Whr  = (const float*)d_in[9];
    const float* bhr  = (const float*)d_in[10];
    const float* Wfr  = (const float*)d_in[11];
    const float* bfr  = (const float*)d_in[12];
    const float* Wwc  = (const float*)d_in[13];
    const float* bwc  = (const float*)d_in[14];
    const float* Wih  = (const float*)d_in[15];
    const float* Whh  = (const float*)d_in[16];
    const float* bih  = (const float*)d_in[17];
    const float* bhh  = (const float*)d_in[18];
    const float* Wih2 = (const float*)d_in[19];
    const float* Whh2 = (const float*)d_in[20];
    const float* bih2 = (const float*)d_in[21];
    const float* bhh2 = (const float*)d_in[22];
    const float* Wo   = (const float*)d_in[23];
    const float* bo   = (const float*)d_in[24];
    float* out = (float*)d_out;

    cudaFuncSetAttribute(brits_kernel, cudaFuncAttributeMaxDynamicSharedMemorySize, SMEM_BYTES);

    repack_kernel<<<960, 256>>>(Wdh, Whr, Wfr, Wwc, Wih, Whh, Wih2, Whh2,
                                bdh, Wdx, bdx, bhr, bfr, bwc,
                                bih, bhh, bih2, bhh2, Wo, bo);
    msum_kernel<<<SEQB, 256>>>(masks);
    brits_kernel<<<NCTA, NTHR, SMEM_BYTES>>>(values, masks, deltas, out);
    finalize_kernel<<<1, 32>>>(out);
}

// round 7
// speedup vs baseline: 1.2431x; 1.0031x over previous
#include <cuda_runtime.h>

#define FEAT 161
#define HID  176
#define SEQB 456
#define NTHR 704
#define NCTA 128
#define NCLUS 64

// ---- float2-packed transposed weight offsets (float units) ----
// layout per region: float2 element (pair p, col c) at base + (p*Cp + c)*2
#define A1  0        // Wdh : 82 pairs, Cp=176
#define A2  28864    // Whr : 88 pairs, Cp=164
#define A3  57728    // Wfr : 82 pairs, Cp=164
#define A4  84624    // Wwc gx seg: 82 pairs, Cp=164
#define A4b 111520   // Wwc m  seg: 82 pairs, Cp=164
#define A5  138416   // LSTM1 cc seg: 82 pairs, Cp=704 (cols permuted)
#define A5m 253872   // LSTM1 m  seg: 82 pairs, Cp=704
#define A5h 369328   // LSTM1 h0 seg: 88 pairs, Cp=704
#define A6  493232   // LSTM2 h0 seg: 88 pairs, Cp=704
#define A6h 617136   // LSTM2 hd seg: 88 pairs, Cp=704
#define WT_TOTAL 741040

// ---- bias offsets ----
#define B_bdh 0
#define B_wdx 176
#define B_bdx 337
#define B_bhr 498
#define B_bfr 659
#define B_bwc 820
#define B_b1  981
#define B_b2  1685
#define B_Wo  2389
#define B_bo  2565
#define B_TOTAL 2566

#define SMEM_BYTES 103808

__device__ float g_WT[WT_TOTAL];
__device__ float g_B[B_TOTAL];
__device__ float g_inv_msum[SEQB];
__device__ float g_lossp[NCLUS];

// ============================= repack =====================================
__global__ void repack_kernel(
    const float* __restrict__ Wdh, const float* __restrict__ Whr,
    const float* __restrict__ Wfr, const float* __restrict__ Wwc,
    const float* __restrict__ Wih, const float* __restrict__ Whh,
    const float* __restrict__ Wih2, const float* __restrict__ Whh2,
    const float* __restrict__ bdh, const float* __restrict__ Wdx,
    const float* __restrict__ bdx, const float* __restrict__ bhr,
    const float* __restrict__ bfr, const float* __restrict__ bwc,
    const float* __restrict__ bih, const float* __restrict__ bhh,
    const float* __restrict__ bih2, const float* __restrict__ bhh2,
    const float* __restrict__ Wo, const float* __restrict__ bo)
{
    int stride = gridDim.x * blockDim.x;
    for (int idx = blockIdx.x * blockDim.x + threadIdx.x; idx < WT_TOTAL; idx += stride) {
        float v = 0.0f;
        int base, Cp, region;
        if      (idx < A2)  { base = A1;  Cp = 176; region = 0; }
        else if (idx < A3)  { base = A2;  Cp = 164; region = 1; }
        else if (idx < A4)  { base = A3;  Cp = 164; region = 2; }
        else if (idx < A4b) { base = A4;  Cp = 164; region = 3; }
        else if (idx < A5)  { base = A4b; Cp = 164; region = 4; }
        else if (idx < A5m) { base = A5;  Cp = 704; region = 5; }
        else if (idx < A5h) { base = A5m; Cp = 704; region = 6; }
        else if (idx < A6)  { base = A5h; Cp = 704; region = 7; }
        else if (idx < A6h) { base = A6;  Cp = 704; region = 8; }
        else                { base = A6h; Cp = 704; region = 9; }
        int j = idx - base, pc = j >> 1, half = j & 1;
        int p = pc / Cp, c = pc % Cp;
        int k = 2 * p + half;
        if (region >= 5) {
            // permuted LSTM column -> original gate row
            int rk = c / 352, rem = c % 352, q = rem / 88, jl = rem % 88;
            int r = q * 176 + rk * 88 + jl;
            switch (region) {
                case 5: if (k < 161) v = Wih[r * 322 + k]; break;
                case 6: if (k < 161) v = Wih[r * 322 + 161 + k]; break;
                case 7: v = Whh[r * 176 + k]; break;
                case 8: v = Wih2[r * 176 + k]; break;
                case 9: v = Whh2[r * 176 + k]; break;
            }
        } else {
            switch (region) {
                case 0: if (k < 161) v = Wdh[c * 161 + k]; break;
                case 1: if (c < 161) v = Whr[c * 176 + k]; break;
                case 2: if (c < 161 && k < 161 && k != c) v = Wfr[c * 161 + k]; break;
                case 3: if (c < 161 && k < 161) v = Wwc[c * 322 + k]; break;
                case 4: if (c < 161 && k < 161) v = Wwc[c * 322 + 161 + k]; break;
            }
        }
        g_WT[idx] = v;
    }
    for (int idx = blockIdx.x * blockDim.x + threadIdx.x; idx < B_TOTAL; idx += stride) {
        float v;
        if (idx < 176)        v = bdh[idx];
        else if (idx < 337)   { int f = idx - 176; v = Wdx[f * 161 + f]; }
        else if (idx < 498)   v = bdx[idx - 337];
        else if (idx < 659)   v = bhr[idx - 498];
        else if (idx < 820)   v = bfr[idx - 659];
        else if (idx < 981)   v = bwc[idx - 820];
        else if (idx < 1685)  {
            int j = idx - 981;
            int rk = j / 352, rem = j % 352, q = rem / 88, jl = rem % 88;
            int r = q * 176 + rk * 88 + jl;
            v = bih[r] + bhh[r];
        } else if (idx < 2389) {
            int j = idx - 1685;
            int rk = j / 352, rem = j % 352, q = rem / 88, jl = rem % 88;
            int r = q * 176 + rk * 88 + jl;
            v = bih2[r] + bhh2[r];
        }
        else if (idx < 2565)  v = Wo[idx - 2389];
        else                  v = bo[0];
        g_B[idx] = v;
    }
}

// ========================== msum precompute ===============================
__global__ void msum_kernel(const float* __restrict__ masks)
{
    __shared__ float red[256];
    int t = blockIdx.x;
    float s = 0.0f;
    for (int idx = threadIdx.x; idx < 512 * FEAT; idx += 256) {
        int b = idx / FEAT, f = idx - b * FEAT;
        s += masks[(b * SEQB + t) * FEAT + f];
    }
    red[threadIdx.x] = s;
    __syncthreads();
    for (int o = 128; o > 0; o >>= 1) {
        if (threadIdx.x < o) red[threadIdx.x] += red[threadIdx.x + o];
        __syncthreads();
    }
    if (threadIdx.x == 0) g_inv_msum[t] = 1.0f / (red[0] + 1e-5f);
}

// ========================== helpers =======================================
__device__ __forceinline__ float sigfast(float x)
{ return __fdividef(1.0f, 1.0f + __expf(-x)); }
__device__ __forceinline__ float tanhfast(float x)
{ return __fdividef(2.0f, 1.0f + __expf(-2.0f * x)) - 1.0f; }

__device__ __forceinline__ void st_peer(float* p, float v, int peer)
{
    unsigned int a = (unsigned int)__cvta_generic_to_shared(p);
    unsigned int ra;
    asm("mapa.shared::cluster.u32 %0, %1, %2;" : "=r"(ra) : "r"(a), "r"(peer));
    asm volatile("st.shared::cluster.f32 [%0], %1;" :: "r"(ra), "f"(v));
}

#define CSYNC() do { \
    asm volatile("barrier.cluster.arrive.aligned;" ::: "memory"); \
    asm volatile("barrier.cluster.wait.aligned;" ::: "memory"); } while (0)

#define FMA2(a, b, c) asm("fma.rn.f32x2 %0, %1, %2, %0;" : "+l"(a) : "l"(b), "l"(c))

// f32x2 GEMV over k-pair range [p0,p1): weights float2 [pair][Cp], input pk[k][8]
__device__ __forceinline__ void gemv8(unsigned long long acc[4],
                                      const float* __restrict__ wbase, int Cp, int col,
                                      const float* __restrict__ pk, int p0, int p1)
{
    const float2* wp = (const float2*)wbase + (size_t)p0 * Cp + col;
    const ulonglong2* ip = (const ulonglong2*)pk + 4 * p0;
#pragma unroll 4
    for (int p = p0; p < p1; p++) {
        float2 w = *wp; wp += Cp;
        ulonglong2 e0 = ip[0], e1 = ip[1], o0 = ip[2], o1 = ip[3]; ip += 4;
        unsigned long long wx, wy;
        asm("mov.b64 %0, {%1, %1};" : "=l"(wx) : "r"(__float_as_uint(w.x)));
        asm("mov.b64 %0, {%1, %1};" : "=l"(wy) : "r"(__float_as_uint(w.y)));
        FMA2(acc[0], wx, e0.x); FMA2(acc[1], wx, e0.y);
        FMA2(acc[2], wx, e1.x); FMA2(acc[3], wx, e1.y);
        FMA2(acc[0], wy, o0.x); FMA2(acc[1], wy, o0.y);
        FMA2(acc[2], wy, o1.x); FMA2(acc[3], wy, o1.y);
    }
}

// ========================== main persistent kernel ========================
struct __align__(16) SM {
    float d[164][8], m[164][8], x[164][8], gx[164][8];
    float xc[164][8], cc[164][8], xh[164][8], zh[164][8], al[164][8];
    float hd[176][8];
    float h0[2][176][8], hR[2][176][8];
    float c0[88][8], c1[88][8];
    float part[8][712];
};

__device__ __forceinline__ void store_part(SM* sm, int u, const unsigned long long acc[4])
{
#pragma unroll
    for (int bp = 0; bp < 4; bp++) {
        unsigned int lo, hi;
        asm("mov.b64 {%0, %1}, %2;" : "=r"(lo), "=r"(hi) : "l"(acc[bp]));
        sm->part[2 * bp][u]     = __uint_as_float(lo);
        sm->part[2 * bp + 1][u] = __uint_as_float(hi);
    }
}

__global__ void __launch_bounds__(NTHR, 1) __cluster_dims__(2, 1, 1)
brits_kernel(const float* __restrict__ values, const float* __restrict__ masks,
             const float* __restrict__ deltas, float* __restrict__ out)
{
    extern __shared__ char dynbuf[];
    SM* sm = (SM*)dynbuf;
    const int tid = threadIdx.x;
    unsigned int rank;
    asm("mov.u32 %0, %%cluster_ctarank;" : "=r"(rank));
    const int peer = (int)(rank ^ 1u);
    const int cid = blockIdx.x >> 1;
    const int b0 = cid * 8;

    // zero all shared state
    {
        float* sp = (float*)sm;
        for (int i = tid; i < SMEM_BYTES / 4; i += NTHR) sp[i] = 0.0f;
    }

    // prefetch slots: s0 = tid, s1 = tid + 704 (slots over 8b x 164f)
    const int s0 = tid,        b_0 = s0 / 164, f_0 = s0 % 164;
    const int s1 = tid + NTHR, b_1 = s1 / 164, f_1 = s1 % 164;
    const bool v0 = (f_0 < 161);
    const bool v1 = (s1 < 1312) && (f_1 < 161);
    float wdx0 = 0.f, bdx0 = 0.f, wdx1 = 0.f, bdx1 = 0.f;
    if (v0) { wdx0 = g_B[B_wdx + f_0]; bdx0 = g_B[B_bdx + f_0]; }
    if (v1) { wdx1 = g_B[B_wdx + f_1]; bdx1 = g_B[B_bdx + f_1]; }

    float px0 = 0.f, pm0 = 0.f, pd0 = 0.f, px1 = 0.f, pm1 = 0.f, pd1 = 0.f;
    if (v0) {
        int off = ((b0 + b_0) * SEQB + 0) * FEAT + f_0;
        px0 = values[off]; pm0 = masks[off]; pd0 = deltas[off];
    }
    if (v1) {
        int off = ((b0 + b_1) * SEQB + 0) * FEAT + f_1;
        px1 = values[off]; pm1 = masks[off]; pd1 = deltas[off];
    }

    // chunk bounds
    const int pb82[5] = {0, 21, 42, 62, 82};
    const int pb88[5] = {0, 22, 44, 66, 88};

    float lossAcc = 0.0f;
    __syncthreads();

    for (int t = 0; t < SEQB; t++) {
        const float lw = (rank == 0) ? g_inv_msum[t] : 0.0f;

        // P0: commit prefetched x/m/d(+gamma_x), issue next prefetch
        if (v0) {
            sm->x[f_0][b_0] = px0; sm->m[f_0][b_0] = pm0; sm->d[f_0][b_0] = pd0;
            sm->gx[f_0][b_0] = __expf(-fmaxf(pd0 * wdx0 + bdx0, 0.0f));
        }
        if (v1) {
            sm->x[f_1][b_1] = px1; sm->m[f_1][b_1] = pm1; sm->d[f_1][b_1] = pd1;
            sm->gx[f_1][b_1] = __expf(-fmaxf(pd1 * wdx1 + bdx1, 0.0f));
        }
        {
            int tn = (t + 1 < SEQB) ? t + 1 : SEQB - 1;
            if (v0) {
                int off = ((b0 + b_0) * SEQB + tn) * FEAT + f_0;
                px0 = values[off]; pm0 = masks[off]; pd0 = deltas[off];
            }
            if (v1) {
                int off = ((b0 + b_1) * SEQB + tn) * FEAT + f_1;
                px1 = values[off]; pm1 = masks[off]; pd1 = deltas[off];
            }
        }
        __syncthreads();

        // PA: Wdh gemv (176 rows x 4 k-chunks)
        {
            int kc = tid / 176, row = tid % 176;
            unsigned long long acc[4] = {0, 0, 0, 0};
            gemv8(acc, g_WT + A1, 176, row, &sm->d[0][0], pb82[kc], pb82[kc + 1]);
            store_part(sm, kc * 176 + row, acc);
        }
        __syncthreads();

        // PC1: gamma_h combine -> decayed h
        for (int u = tid; u < 1408; u += NTHR) {
            int j = u % 176, b = u / 176;
            float s = sm->part[b][j] + sm->part[b][176 + j]
                    + sm->part[b][352 + j] + sm->part[b][528 + j] + g_B[B_bdh + j];
            float gh = __expf(-fmaxf(s, 0.0f));
            sm->hd[j][b] = sm->hR[t & 1][j][b] * gh;
        }
        __syncthreads();

        // PB: Wwc gemv (161 rows x 4 chunks: 2 over gx, 2 over m)
        if (tid < 656) {
            int kc = tid / 164, row = tid % 164;
            if (row < 161) {
                unsigned long long acc[4] = {0, 0, 0, 0};
                if (kc < 2)
                    gemv8(acc, g_WT + A4,  164, row, &sm->gx[0][0], kc * 41, kc * 41 + 41);
                else
                    gemv8(acc, g_WT + A4b, 164, row, &sm->m[0][0], (kc - 2) * 41, (kc - 2) * 41 + 41);
                store_part(sm, kc * 164 + row, acc);
            }
        }
        __syncthreads();

        // PBc: alpha combine
        for (int u = tid; u < 1288; u += NTHR) {
            int f = u % 161, b = u / 161;
            sm->al[f][b] = sm->part[b][f] + sm->part[b][164 + f]
                         + sm->part[b][328 + f] + sm->part[b][492 + f] + g_B[B_bwc + f];
        }
        __syncthreads();

        // P2: Whr gemv (input hd, 88 pairs x 4 chunks)
        if (tid < 656) {
            int kc = tid / 164, row = tid % 164;
            if (row < 161) {
                unsigned long long acc[4] = {0, 0, 0, 0};
                gemv8(acc, g_WT + A2, 164, row, &sm->hd[0][0], pb88[kc], pb88[kc + 1]);
                store_part(sm, kc * 164 + row, acc);
            }
        }
        __syncthreads();

        // P2b: x_h, loss1, x_c
        for (int u = tid; u < 1288; u += NTHR) {
            int f = u % 161, b = u / 161;
            float xh = sm->part[b][f] + sm->part[b][164 + f]
                     + sm->part[b][328 + f] + sm->part[b][492 + f] + g_B[B_bhr + f];
            float x = sm->x[f][b], m = sm->m[f][b];
            lossAcc += fabsf(x - xh) * m * lw;
            sm->xh[f][b] = xh;
            sm->xc[f][b] = m * x + (1.0f - m) * xh;
        }
        __syncthreads();

        // P3: Wfr gemv (input xc)
        if (tid < 656) {
            int kc = tid / 164, row = tid % 164;
            if (row < 161) {
                unsigned long long acc[4] = {0, 0, 0, 0};
                gemv8(acc, g_WT + A3, 164, row, &sm->xc[0][0], pb82[kc], pb82[kc + 1]);
                store_part(sm, kc * 164 + row, acc);
            }
        }
        __syncthreads();

        // P3b: z_h, loss2
        for (int u = tid; u < 1288; u += NTHR) {
            int f = u % 161, b = u / 161;
            float zh = sm->part[b][f] + sm->part[b][164 + f]
                     + sm->part[b][328 + f] + sm->part[b][492 + f] + g_B[B_bfr + f];
            sm->zh[f][b] = zh;
            lossAcc += fabsf(sm->x[f][b] - zh) * sm->m[f][b] * lw;
        }
        __syncthreads();

        // P4b: c_h, loss3, c_c + imputation store
        for (int u = tid; u < 1288; u += NTHR) {
            int f = u % 161, b = u / 161;
            float al = sm->al[f][b];
            float xh = sm->xh[f][b];
            float ch = xh + al * (sm->zh[f][b] - xh);
            float x = sm->x[f][b], m = sm->m[f][b];
            lossAcc += fabsf(x - ch) * m * lw;
            float cc = m * x + (1.0f - m) * ch;
            sm->cc[f][b] = cc;
            if ((b >> 2) == (int)rank)
                out[513 + ((b0 + b) * SEQB + t) * FEAT + f] = cc;
        }
        __syncthreads();

        // P5: LSTM1 gates (352 local rows x 2 k-chunks)
        {
            int kh = tid / 352, lrow = tid % 352;
            int col = (int)rank * 352 + lrow;
            unsigned long long acc[4] = {0, 0, 0, 0};
            if (kh == 0) {
                gemv8(acc, g_WT + A5,  704, col, &sm->cc[0][0], 0, 82);
                gemv8(acc, g_WT + A5m, 704, col, &sm->m[0][0],  0, 44);
            } else {
                gemv8(acc, g_WT + A5m, 704, col, &sm->m[0][0], 44, 82);
                gemv8(acc, g_WT + A5h, 704, col, &sm->h0[t & 1][0][0], 0, 88);
            }
            store_part(sm, kh * 352 + lrow, acc);
        }
        __syncthreads();

        // P6: LSTM1 elementwise -> h0 new (own half, local + peer store)
        {
            int jl = tid % 88, b = tid / 88;
            float g0 = sm->part[b][jl]       + sm->part[b][352 + jl]       + g_B[B_b1 + (int)rank * 352 + jl];
            float g1 = sm->part[b][88 + jl]  + sm->part[b][352 + 88 + jl]  + g_B[B_b1 + (int)rank * 352 + 88 + jl];
            float g2 = sm->part[b][176 + jl] + sm->part[b][352 + 176 + jl] + g_B[B_b1 + (int)rank * 352 + 176 + jl];
            float g3 = sm->part[b][264 + jl] + sm->part[b][352 + 264 + jl] + g_B[B_b1 + (int)rank * 352 + 264 + jl];
            float i_ = sigfast(g0), f_ = sigfast(g1), gg = tanhfast(g2), o_ = sigfast(g3);
            float c = f_ * sm->c0[jl][b] + i_ * gg;
            sm->c0[jl][b] = c;
            float h0v = o_ * tanhfast(c);
            int idx = (int)rank * 88 + jl;
            sm->h0[(t + 1) & 1][idx][b] = h0v;
            st_peer(&sm->h0[(t + 1) & 1][idx][b], h0v, peer);
        }
        CSYNC();

        // P7: LSTM2 gates
        {
            int kh = tid / 352, lrow = tid % 352;
            int col = (int)rank * 352 + lrow;
            unsigned long long acc[4] = {0, 0, 0, 0};
            if (kh == 0)
                gemv8(acc, g_WT + A6,  704, col, &sm->h0[(t + 1) & 1][0][0], 0, 88);
            else
                gemv8(acc, g_WT + A6h, 704, col, &sm->hd[0][0], 0, 88);
            store_part(sm, kh * 352 + lrow, acc);
        }
        __syncthreads();

        // P8: LSTM2 elementwise -> h new (own half, local + peer store)
        {
            int jl = tid % 88, b = tid / 88;
            float g0 = sm->part[b][jl]       + sm->part[b][352 + jl]       + g_B[B_b2 + (int)rank * 352 + jl];
            float g1 = sm->part[b][88 + jl]  + sm->part[b][352 + 88 + jl]  + g_B[B_b2 + (int)rank * 352 + 88 + jl];
            float g2 = sm->part[b][176 + jl] + sm->part[b][352 + 176 + jl] + g_B[B_b2 + (int)rank * 352 + 176 + jl];
            float g3 = sm->part[b][264 + jl] + sm->part[b][352 + 264 + jl] + g_B[B_b2 + (int)rank * 352 + 264 + jl];
            float i_ = sigfast(g0), f_ = sigfast(g1), gg = tanhfast(g2), o_ = sigfast(g3);
            float c = f_ * sm->c1[jl][b] + i_ * gg;
            sm->c1[jl][b] = c;
            float hv = o_ * tanhfast(c);
            int idx = (int)rank * 88 + jl;
            sm->hR[(t + 1) & 1][idx][b] = hv;
            st_peer(&sm->hR[(t + 1) & 1][idx][b], hv, peer);
        }
        CSYNC();
    }

    // predictions: final h is in hR[SEQB & 1] == hR[0]
    if (rank == 0 && tid < 256) {
        int b = tid >> 5, lane = tid & 31;
        float s = 0.0f;
        for (int j = lane; j < 176; j += 32) s += sm->hR[0][j][b] * g_B[B_Wo + j];
        for (int o = 16; o; o >>= 1) s += __shfl_down_sync(0xffffffffu, s, o);
        if (lane == 0) out[1 + b0 + b] = sigfast(s + g_B[B_bo]);
    }

    // loss partial
    {
        float* lr = &sm->part[0][0];
        lr[tid] = lossAcc;
        __syncthreads();
        if (tid == 0 && rank == 0) {
            float s = 0.0f;
            for (int i = 0; i < NTHR; i++) s += lr[i];
            g_lossp[cid] = s;
        }
    }
}

__global__ void finalize_kernel(float* __restrict__ out)
{
    if (threadIdx.x == 0 && blockIdx.x == 0) {
        float s = 0.0f;
        for (int i = 0; i < NCLUS; i++) s += g_lossp[i];
        out[0] = s / (float)SEQB;
    }
}

extern "C" void kernel_launch(void* const* d_in, const int* in_sizes, int n_in,
                              void* d_out, int out_size)
{
    const float* values = (const float*)d_in[0];
    const float* masks  = (const float*)d_in[1];
    const float* deltas = (const float*)d_in[2];
    const float* Wdh  = (const float*)d_in[5];
    const float* bdh  = (const float*)d_in[6];
    const float* Wdx  = (const float*)d_in[7];
    const float* bdx  = (const float*)d_in[8];
    const float* Whr  = (const float*)d_in[9];
    const float* bhr  = (const float*)d_in[10];
    const float* Wfr  = (const float*)d_in[11];
    const float* bfr  = (const float*)d_in[12];
    const float* Wwc  = (const float*)d_in[13];
    const float* bwc  = (const float*)d_in[14];
    const float* Wih  = (const float*)d_in[15];
    const float* Whh  = (const float*)d_in[16];
    const float* bih  = (const float*)d_in[17];
    const float* bhh  = (const float*)d_in[18];
    const float* Wih2 = (const float*)d_in[19];
    const float* Whh2 = (const float*)d_in[20];
    const float* bih2 = (const float*)d_in[21];
    const float* bhh2 = (const float*)d_in[22];
    const float* Wo   = (const float*)d_in[23];
    const float* bo   = (const float*)d_in[24];
    float* out = (float*)d_out;

    cudaFuncSetAttribute(brits_kernel, cudaFuncAttributeMaxDynamicSharedMemorySize, SMEM_BYTES);

    repack_kernel<<<960, 256>>>(Wdh, Whr, Wfr, Wwc, Wih, Whh, Wih2, Whh2,
                                bdh, Wdx, bdx, bhr, bfr, bwc,
                                bih, bhh, bih2, bhh2, Wo, bo);
    msum_kernel<<<SEQB, 256>>>(masks);
    brits_kernel<<<NCTA, NTHR, SMEM_BYTES>>>(values, masks, deltas, out);
    finalize_kernel<<<1, 32>>>(out);
}